// round 5
// baseline (speedup 1.0000x reference)
#include <cuda_runtime.h>
#include <math.h>
#include <stdint.h>

typedef unsigned long long ull;

// ---------------- problem constants ----------------
#define B   64
#define T   256
#define D   2048
#define H   1024
#define G3  3072
#define NC  1000
#define BT  (B*T)

#define FMA_F32X2(acc, a, b) \
    asm("fma.rn.f32x2 %0, %1, %2, %0;" : "+l"(acc) : "l"(a), "l"(b))

__device__ __forceinline__ float f2lo(ull v) { return __uint_as_float((unsigned)(v & 0xffffffffULL)); }
__device__ __forceinline__ float f2hi(ull v) { return __uint_as_float((unsigned)(v >> 32)); }

// ---------------- device scratch ----------------
__device__ __align__(16) float g_M2 [3*2048];            // [g][i1i2(32)][o1o2r2(64)]
__device__ __align__(16) float g_M34[3*16384];           // [g][r2][i3i4][o3o4] == [g][k(256)][64]
__device__ __align__(16) float g_UT [(size_t)G3*H];      // U^T: [j][k]
__device__ __align__(16) float g_P  [(size_t)BT*12288];  // [bt][g][o1o2][r2*64+i3i4]
__device__ __align__(16) float g_gi [(size_t)BT*G3];     // [t][b][3H]
__device__ __align__(16) float g_h  [2][B*H];            // ping-pong hidden [b][k]
__device__ unsigned g_barc;
__device__ unsigned g_barg;

// ---------------- init ----------------
__global__ void init_kernel() {
    int idx = blockIdx.x * blockDim.x + threadIdx.x;
    for (int i = idx; i < B*H; i += gridDim.x * blockDim.x) g_h[0][i] = 0.f;
    if (idx == 0) { g_barc = 0u; g_barg = 0u; }
}

// ---------------- build M2, M34 from TT cores ----------------
__global__ void build_M_kernel(const float* __restrict__ c0,
                               const float* __restrict__ c1,
                               const float* __restrict__ c2,
                               const float* __restrict__ c3) {
    for (int idx = threadIdx.x; idx < 3*2048; idx += blockDim.x) {
        int r2 = idx & 3, o2 = (idx>>2)&3, o1 = (idx>>4)&3;
        int i2 = (idx>>6)&7, i1 = (idx>>9)&3, g = idx>>11;
        float s = 0.f;
        #pragma unroll
        for (int r1 = 0; r1 < 4; ++r1)
            s += c0[g*64 + i1*16 + o1*4 + r1] *
                 c1[g*512 + r1*128 + i2*16 + o2*4 + r2];
        g_M2[idx] = s;
    }
    for (int idx = threadIdx.x; idx < 3*16384; idx += blockDim.x) {
        int o4 = idx & 7, o3 = (idx>>3)&7, i4 = (idx>>6)&7;
        int i3 = (idx>>9)&7, r2 = (idx>>12)&3, g = idx>>14;
        float s = 0.f;
        #pragma unroll
        for (int r3 = 0; r3 < 4; ++r3)
            s += c2[g*1024 + r2*256 + i3*32 + o3*4 + r3] *
                 c3[g*256  + r3*64  + i4*8  + o4];
        g_M34[idx] = s;
    }
}

// ---------------- transpose U [H,G3] -> UT [G3,H] ----------------
__global__ void build_UT_kernel(const float* __restrict__ U) {
    __shared__ float s[32][33];
    int j0 = blockIdx.x * 32;
    int k0 = blockIdx.y * 32;
    int tx = threadIdx.x, ty = threadIdx.y;
    #pragma unroll
    for (int r = ty; r < 32; r += 8)
        s[r][tx] = U[(size_t)(k0 + r) * G3 + j0 + tx];
    __syncthreads();
    #pragma unroll
    for (int r = ty; r < 32; r += 8)
        g_UT[(size_t)(j0 + r) * H + k0 + tx] = s[tx][r];
}

// ---------------- TT stage A ----------------
// P[bt][(g,o1o2,r2)=r(192)][i3i4(64)] = sum_{i1i2} v[bt][i1i2][i3i4] * M2[g][i1i2][ocr]
// grid: 2048 blocks x 8 bt, 256 threads; warp w -> bt w, lane l -> i3i4 pair l.
#define TTA_SMEM (32*192*8 + 8*2048*4)   // sM dup 49152 + sV 65536 = 114688
__global__ void __launch_bounds__(256)
ttA_kernel(const float* __restrict__ X) {
    extern __shared__ __align__(16) float smA[];
    float2* sM = (float2*)smA;                 // [k(32)][r(192)] duplicated
    float*  sV = smA + 2*32*192;               // [bt(8)][2048]

    const int tid = threadIdx.x;
    const int bt0 = blockIdx.x * 8;

    for (int i = tid; i < 32*192; i += 256) {
        int k = i / 192, r = i - k*192;
        int g = r >> 6, ocr = r & 63;
        float v = g_M2[g*2048 + k*64 + ocr];
        sM[k*192 + r] = make_float2(v, v);
    }
    {
        const float4* Xb = (const float4*)(X + (size_t)bt0 * D);
        float4* sv4 = (float4*)sV;
        #pragma unroll
        for (int i = tid; i < 8*2048/4; i += 256) sv4[i] = Xb[i];
    }
    __syncthreads();

    const int bt = tid >> 5;        // warp-uniform
    const int l  = tid & 31;        // i3i4 pair
    const float* vbase = sV + bt * 2048;
    const size_t prow = (size_t)(bt0 + bt) * 12288;

    for (int rg = 0; rg < 24; ++rg) {
        const int r0 = rg * 8;
        ull acc[8] = {0,0,0,0,0,0,0,0};
        #pragma unroll 4
        for (int k = 0; k < 32; ++k) {
            ull vv = *(const ull*)(vbase + k*64 + 2*l);
            const float2* mrow = sM + k*192 + r0;
            #pragma unroll
            for (int j = 0; j < 8; ++j) {
                ull mm = *(const ull*)(mrow + j);
                FMA_F32X2(acc[j], vv, mm);
            }
        }
        #pragma unroll
        for (int j = 0; j < 8; ++j) {
            int r = r0 + j;
            int g = r >> 6, o = (r >> 2) & 15, r2 = r & 3;
            float* dst = g_P + prow + ((size_t)g*16 + o)*256 + r2*64 + 2*l;
            *(float2*)dst = make_float2(f2lo(acc[j]), f2hi(acc[j]));
        }
    }
}

// ---------------- TT stage B ----------------
// per gate g: C[M=BT*16, 64] = P_g[M,256] @ M34g[256,64], + bias, scatter to gi[t][b][3H]
// block tile 128x64, K=256, 256 threads, microtile 8Mx4N (2 f32x2), A dup'd in smem.
__global__ void __launch_bounds__(256)
ttB_kernel(const float* __restrict__ bi) {
    __shared__ __align__(16) float2 Asd[2][16][128];   // dup A: [k][row]  32KB
    __shared__ __align__(16) float  Bs [2][16][64];    //                   8KB

    const int tid = threadIdx.x;
    const int g   = blockIdx.y;
    const int m0  = blockIdx.x * 128;
    const int tx  = tid & 15;      // N: cols tx*4..+3
    const int ty  = tid >> 4;      // M: rows ty*8..+7

    // staging assignment
    const int row0 = tid >> 2;             // 0..63
    const int kq   = (tid & 3) * 4;        // 0,4,8,12
    const int row1 = row0 + 64;
    const int bkr  = tid >> 4;             // B k-row 0..15
    const int bcc  = (tid & 15) * 4;       // B col

    const int mA0 = m0 + row0, mA1 = m0 + row1;
    const size_t offA0 = ((size_t)(mA0 >> 4) * 48 + g*16 + (mA0 & 15)) * 256;
    const size_t offA1 = ((size_t)(mA1 >> 4) * 48 + g*16 + (mA1 & 15)) * 256;
    const float* Mg = g_M34 + (size_t)g * 16384;

    ull acc[8][2];
    #pragma unroll
    for (int i = 0; i < 8; ++i) { acc[i][0] = 0ULL; acc[i][1] = 0ULL; }

    float4 a0 = *(const float4*)(g_P + offA0 + kq);
    float4 a1 = *(const float4*)(g_P + offA1 + kq);
    float4 b4 = *(const float4*)(Mg + (size_t)bkr * 64 + bcc);

    // stage tile 0
    Asd[0][kq+0][row0] = make_float2(a0.x, a0.x);
    Asd[0][kq+1][row0] = make_float2(a0.y, a0.y);
    Asd[0][kq+2][row0] = make_float2(a0.z, a0.z);
    Asd[0][kq+3][row0] = make_float2(a0.w, a0.w);
    Asd[0][kq+0][row1] = make_float2(a1.x, a1.x);
    Asd[0][kq+1][row1] = make_float2(a1.y, a1.y);
    Asd[0][kq+2][row1] = make_float2(a1.z, a1.z);
    Asd[0][kq+3][row1] = make_float2(a1.w, a1.w);
    *(float4*)&Bs[0][bkr][bcc] = b4;
    __syncthreads();

    int buf = 0;
    for (int kt = 0; kt < 16; ++kt) {
        if (kt < 15) {
            int k0 = (kt + 1) * 16;
            a0 = *(const float4*)(g_P + offA0 + k0 + kq);
            a1 = *(const float4*)(g_P + offA1 + k0 + kq);
            b4 = *(const float4*)(Mg + (size_t)(k0 + bkr) * 64 + bcc);
        }
        #pragma unroll
        for (int k = 0; k < 16; ++k) {
            const float2* ap = &Asd[buf][k][ty*8];
            ulonglong2 A01 = *(const ulonglong2*)(ap);
            ulonglong2 A23 = *(const ulonglong2*)(ap + 2);
            ulonglong2 A45 = *(const ulonglong2*)(ap + 4);
            ulonglong2 A67 = *(const ulonglong2*)(ap + 6);
            ulonglong2 Bv  = *(const ulonglong2*)&Bs[buf][k][tx*4];
            FMA_F32X2(acc[0][0], A01.x, Bv.x); FMA_F32X2(acc[0][1], A01.x, Bv.y);
            FMA_F32X2(acc[1][0], A01.y, Bv.x); FMA_F32X2(acc[1][1], A01.y, Bv.y);
            FMA_F32X2(acc[2][0], A23.x, Bv.x); FMA_F32X2(acc[2][1], A23.x, Bv.y);
            FMA_F32X2(acc[3][0], A23.y, Bv.x); FMA_F32X2(acc[3][1], A23.y, Bv.y);
            FMA_F32X2(acc[4][0], A45.x, Bv.x); FMA_F32X2(acc[4][1], A45.x, Bv.y);
            FMA_F32X2(acc[5][0], A45.y, Bv.x); FMA_F32X2(acc[5][1], A45.y, Bv.y);
            FMA_F32X2(acc[6][0], A67.x, Bv.x); FMA_F32X2(acc[6][1], A67.x, Bv.y);
            FMA_F32X2(acc[7][0], A67.y, Bv.x); FMA_F32X2(acc[7][1], A67.y, Bv.y);
        }
        if (kt < 15) {
            int nb = buf ^ 1;
            Asd[nb][kq+0][row0] = make_float2(a0.x, a0.x);
            Asd[nb][kq+1][row0] = make_float2(a0.y, a0.y);
            Asd[nb][kq+2][row0] = make_float2(a0.z, a0.z);
            Asd[nb][kq+3][row0] = make_float2(a0.w, a0.w);
            Asd[nb][kq+0][row1] = make_float2(a1.x, a1.x);
            Asd[nb][kq+1][row1] = make_float2(a1.y, a1.y);
            Asd[nb][kq+2][row1] = make_float2(a1.z, a1.z);
            Asd[nb][kq+3][row1] = make_float2(a1.w, a1.w);
            *(float4*)&Bs[nb][bkr][bcc] = b4;
        }
        __syncthreads();
        buf ^= 1;
    }

    // epilogue: bias + scatter to gi[t][b][3H]
    #pragma unroll
    for (int i = 0; i < 8; ++i) {
        int m  = m0 + ty*8 + i;
        int bt = m >> 4, oo = m & 15;
        int bb = bt >> 8, tt = bt & 255;
        const float* bp = bi + g*1024 + oo*64 + tx*4;
        float4 out;
        out.x = f2lo(acc[i][0]) + bp[0];
        out.y = f2hi(acc[i][0]) + bp[1];
        out.z = f2lo(acc[i][1]) + bp[2];
        out.w = f2hi(acc[i][1]) + bp[3];
        float* dst = g_gi + ((size_t)tt * B + bb) * G3 + g*1024 + oo*64 + tx*4;
        *(float4*)dst = out;
    }
}

// ---------------- persistent scan ----------------
#define SCAN_BLOCKS 128
#define US_STRIDE 1036                     // U row stride (floats), conflict-free
#define KC 512
#define SH_STRIDE 516                      // h row stride (floats)
#define SCAN_SMEM (24*US_STRIDE*4 + 64*SH_STRIDE*4)   // 99456 + 132096 = 231552

__global__ void __launch_bounds__(256, 1)
scan_kernel(const float* __restrict__ bh) {
    extern __shared__ __align__(16) float smem[];
    float* Us = smem;                      // [24][US_STRIDE]
    float* sH = smem + 24*US_STRIDE;       // [64][SH_STRIDE]

    const int tid    = threadIdx.x;
    const int oloc   = tid & 7;
    const int bslot  = tid >> 3;           // 0..31
    const int blk_o0 = blockIdx.x * 8;
    const int o      = blk_o0 + oloc;
    const int b0     = bslot, b1 = bslot + 32;

    // stage U rows (natural, non-duplicated)
    for (int i = tid; i < 24*1024; i += 256) {
        int r = i >> 10, k = i & 1023;
        int g = r >> 3, ol = r & 7;
        Us[r*US_STRIDE + k] = g_UT[(size_t)(g*H + blk_o0 + ol)*H + k];
    }
    __syncthreads();

    const float bh0 = bh[o], bh1 = bh[H+o], bh2 = bh[2*H+o];
    const float* ur0 = Us + (0*8 + oloc)*US_STRIDE;
    const float* ur1 = Us + (1*8 + oloc)*US_STRIDE;
    const float* ur2 = Us + (2*8 + oloc)*US_STRIDE;

    unsigned* barc = &g_barc;
    unsigned* barg = &g_barg;

    for (int t = 0; t < T; ++t) {
        const float* hc = g_h[t & 1];
        float*       hn = g_h[(t & 1) ^ 1];

        const float* gib = g_gi + (size_t)t * B * G3;
        float gi0a = __ldcg(gib + (size_t)b0*G3 +          o);
        float gi1a = __ldcg(gib + (size_t)b0*G3 + H      + o);
        float gi2a = __ldcg(gib + (size_t)b0*G3 + 2*H    + o);
        float gi0b = __ldcg(gib + (size_t)b1*G3 +          o);
        float gi1b = __ldcg(gib + (size_t)b1*G3 + H      + o);
        float gi2b = __ldcg(gib + (size_t)b1*G3 + 2*H    + o);
        float hoa  = __ldcg(hc + b0*H + o);
        float hob  = __ldcg(hc + b1*H + o);

        ull a0a=0ULL, a1a=0ULL, a2a=0ULL, a0b=0ULL, a1b=0ULL, a2b=0ULL;

        #pragma unroll
        for (int c = 0; c < 2; ++c) {
            const int k0 = c * KC;
            __syncthreads();
            // stage h chunk [64][KC] via L2 (.cg: no stale-L1 hazard)
            for (int i = tid; i < 64*(KC/4); i += 256) {
                int b = i >> 7;               // KC/4 = 128
                int q = i & 127;
                float4 v = __ldcg(((const float4*)(hc + (size_t)b*H + k0)) + q);
                *(float4*)(sH + b*SH_STRIDE + q*4) = v;
            }
            __syncthreads();

            const float* ha = sH + b0*SH_STRIDE;
            const float* hb = sH + b1*SH_STRIDE;
            const float* w0 = ur0 + k0;
            const float* w1 = ur1 + k0;
            const float* w2 = ur2 + k0;

            #pragma unroll 2
            for (int k = 0; k < KC; k += 8) {
                ulonglong2 hA0 = *(const ulonglong2*)(ha + k);
                ulonglong2 hB0 = *(const ulonglong2*)(hb + k);
                ulonglong2 W0a = *(const ulonglong2*)(w0 + k);
                ulonglong2 W1a = *(const ulonglong2*)(w1 + k);
                ulonglong2 W2a = *(const ulonglong2*)(w2 + k);
                FMA_F32X2(a0a, hA0.x, W0a.x); FMA_F32X2(a1a, hA0.x, W1a.x); FMA_F32X2(a2a, hA0.x, W2a.x);
                FMA_F32X2(a0b, hB0.x, W0a.x); FMA_F32X2(a1b, hB0.x, W1a.x); FMA_F32X2(a2b, hB0.x, W2a.x);
                FMA_F32X2(a0a, hA0.y, W0a.y); FMA_F32X2(a1a, hA0.y, W1a.y); FMA_F32X2(a2a, hA0.y, W2a.y);
                FMA_F32X2(a0b, hB0.y, W0a.y); FMA_F32X2(a1b, hB0.y, W1a.y); FMA_F32X2(a2b, hB0.y, W2a.y);
                ulonglong2 hA1 = *(const ulonglong2*)(ha + k + 4);
                ulonglong2 hB1 = *(const ulonglong2*)(hb + k + 4);
                ulonglong2 W0b = *(const ulonglong2*)(w0 + k + 4);
                ulonglong2 W1b = *(const ulonglong2*)(w1 + k + 4);
                ulonglong2 W2b = *(const ulonglong2*)(w2 + k + 4);
                FMA_F32X2(a0a, hA1.x, W0b.x); FMA_F32X2(a1a, hA1.x, W1b.x); FMA_F32X2(a2a, hA1.x, W2b.x);
                FMA_F32X2(a0b, hB1.x, W0b.x); FMA_F32X2(a1b, hB1.x, W1b.x); FMA_F32X2(a2b, hB1.x, W2b.x);
                FMA_F32X2(a0a, hA1.y, W0b.y); FMA_F32X2(a1a, hA1.y, W1b.y); FMA_F32X2(a2a, hA1.y, W2b.y);
                FMA_F32X2(a0b, hB1.y, W0b.y); FMA_F32X2(a1b, hB1.y, W1b.y); FMA_F32X2(a2b, hB1.y, W2b.y);
            }
        }

        // reduce k-pairs, GRU pointwise update
        float A00 = f2lo(a0a) + f2hi(a0a);
        float A01 = f2lo(a1a) + f2hi(a1a);
        float A02 = f2lo(a2a) + f2hi(a2a);
        float A10 = f2lo(a0b) + f2hi(a0b);
        float A11 = f2lo(a1b) + f2hi(a1b);
        float A12 = f2lo(a2b) + f2hi(a2b);

        float r_a = 1.f / (1.f + expf(-(gi0a + A00 + bh0)));
        float z_a = 1.f / (1.f + expf(-(gi1a + A01 + bh1)));
        float n_a = tanhf(gi2a + r_a * (A02 + bh2));
        hn[b0*H + o] = (1.f - z_a) * n_a + z_a * hoa;

        float r_b = 1.f / (1.f + expf(-(gi0b + A10 + bh0)));
        float z_b = 1.f / (1.f + expf(-(gi1b + A11 + bh1)));
        float n_b = tanhf(gi2b + r_b * (A12 + bh2));
        hn[b1*H + o] = (1.f - z_b) * n_b + z_b * hob;

        // grid barrier: release/acquire at L2, no L1 flush, monotone counters
        __syncthreads();
        if (tid == 0) {
            unsigned old;
            asm volatile("atom.add.release.gpu.u32 %0, [%1], 1;"
                         : "=r"(old) : "l"(barc) : "memory");
            unsigned tgt = (unsigned)(t + 1);
            if (old == tgt * SCAN_BLOCKS - 1u) {
                asm volatile("st.release.gpu.u32 [%0], %1;" :: "l"(barg), "r"(tgt) : "memory");
            } else {
                unsigned cur;
                do {
                    asm volatile("ld.acquire.gpu.u32 %0, [%1];" : "=r"(cur) : "l"(barg) : "memory");
                } while (cur < tgt);
            }
        }
        __syncthreads();
    }
}

// ---------------- final FC + ReLU ----------------
__global__ void fc_kernel(const float* __restrict__ Wfc,
                          const float* __restrict__ bfc,
                          float* __restrict__ out) {
    int idx = blockIdx.x * blockDim.x + threadIdx.x;
    if (idx >= B * NC) return;
    int b = idx / NC, c = idx - b * NC;
    const float* h = g_h[0] + (size_t)b * H;   // T even -> final state in buffer 0
    float s0 = bfc[c], s1 = 0.f, s2 = 0.f, s3 = 0.f;
    #pragma unroll 4
    for (int k = 0; k < H; k += 4) {
        float4 hv = *(const float4*)(h + k);
        s0 += hv.x * Wfc[(size_t)(k    ) * NC + c];
        s1 += hv.y * Wfc[(size_t)(k + 1) * NC + c];
        s2 += hv.z * Wfc[(size_t)(k + 2) * NC + c];
        s3 += hv.w * Wfc[(size_t)(k + 3) * NC + c];
    }
    out[idx] = fmaxf((s0 + s1) + (s2 + s3), 0.f);
}

// ---------------- launcher ----------------
extern "C" void kernel_launch(void* const* d_in, const int* in_sizes, int n_in,
                              void* d_out, int out_size) {
    (void)in_sizes; (void)n_in; (void)out_size;
    const float* x    = (const float*)d_in[0];
    const float* c0   = (const float*)d_in[1];
    const float* c1   = (const float*)d_in[2];
    const float* c2   = (const float*)d_in[3];
    const float* c3   = (const float*)d_in[4];
    const float* bi   = (const float*)d_in[5];
    const float* U    = (const float*)d_in[6];
    const float* bh   = (const float*)d_in[7];
    const float* Wfc  = (const float*)d_in[8];
    const float* bfc  = (const float*)d_in[9];

    cudaFuncSetAttribute(ttA_kernel,  cudaFuncAttributeMaxDynamicSharedMemorySize, TTA_SMEM);
    cudaFuncSetAttribute(scan_kernel, cudaFuncAttributeMaxDynamicSharedMemorySize, SCAN_SMEM);

    init_kernel<<<64, 256>>>();
    build_M_kernel<<<1, 256>>>(c0, c1, c2, c3);
    build_UT_kernel<<<dim3(96, 32), dim3(32, 8)>>>(U);
    ttA_kernel<<<2048, 256, TTA_SMEM>>>(x);
    ttB_kernel<<<dim3(2048, 3), 256>>>(bi);
    scan_kernel<<<SCAN_BLOCKS, 256, SCAN_SMEM>>>(bh);
    fc_kernel<<<(B * NC + 255) / 256, 256>>>(Wfc, bfc, (float*)d_out);
}

// round 6
// speedup vs baseline: 1.3212x; 1.3212x over previous
#include <cuda_runtime.h>
#include <math.h>
#include <stdint.h>

typedef unsigned long long ull;

// ---------------- problem constants ----------------
#define B   64
#define T   256
#define D   2048
#define H   1024
#define G3  3072
#define NC  1000
#define BT  (B*T)

#define FMA_F32X2(acc, a, b) \
    asm("fma.rn.f32x2 %0, %1, %2, %0;" : "+l"(acc) : "l"(a), "l"(b))

__device__ __forceinline__ float f2lo(ull v) { return __uint_as_float((unsigned)(v & 0xffffffffULL)); }
__device__ __forceinline__ float f2hi(ull v) { return __uint_as_float((unsigned)(v >> 32)); }

// ---------------- device scratch ----------------
__device__ __align__(16) float g_M2 [3*2048];            // [g][i1i2(32)][o1o2r2(64)]
__device__ __align__(16) float g_M34[3*16384];           // [g][k(256)][64]
__device__ __align__(16) float g_UT [(size_t)G3*H];      // U^T: [j][k]
__device__ __align__(16) float g_P  [(size_t)BT*12288];  // [bt][g][o1o2][r2*64+i3i4]
__device__ __align__(16) float g_gi [(size_t)BT*G3];     // [t][b][3H]
__device__ __align__(16) float g_h  [2][B*H];            // ping-pong hidden [b][k]
__device__ unsigned g_barc;
__device__ unsigned g_barg;

// ---------------- init ----------------
__global__ void init_kernel() {
    int idx = blockIdx.x * blockDim.x + threadIdx.x;
    for (int i = idx; i < B*H; i += gridDim.x * blockDim.x) g_h[0][i] = 0.f;
    if (idx == 0) { g_barc = 0u; g_barg = 0u; }
}

// ---------------- build M2, M34 from TT cores ----------------
__global__ void build_M_kernel(const float* __restrict__ c0,
                               const float* __restrict__ c1,
                               const float* __restrict__ c2,
                               const float* __restrict__ c3) {
    for (int idx = threadIdx.x; idx < 3*2048; idx += blockDim.x) {
        int r2 = idx & 3, o2 = (idx>>2)&3, o1 = (idx>>4)&3;
        int i2 = (idx>>6)&7, i1 = (idx>>9)&3, g = idx>>11;
        float s = 0.f;
        #pragma unroll
        for (int r1 = 0; r1 < 4; ++r1)
            s += c0[g*64 + i1*16 + o1*4 + r1] *
                 c1[g*512 + r1*128 + i2*16 + o2*4 + r2];
        g_M2[idx] = s;
    }
    for (int idx = threadIdx.x; idx < 3*16384; idx += blockDim.x) {
        int o4 = idx & 7, o3 = (idx>>3)&7, i4 = (idx>>6)&7;
        int i3 = (idx>>9)&7, r2 = (idx>>12)&3, g = idx>>14;
        float s = 0.f;
        #pragma unroll
        for (int r3 = 0; r3 < 4; ++r3)
            s += c2[g*1024 + r2*256 + i3*32 + o3*4 + r3] *
                 c3[g*256  + r3*64  + i4*8  + o4];
        g_M34[idx] = s;
    }
}

// ---------------- transpose U [H,G3] -> UT [G3,H] ----------------
__global__ void build_UT_kernel(const float* __restrict__ U) {
    __shared__ float s[32][33];
    int j0 = blockIdx.x * 32;
    int k0 = blockIdx.y * 32;
    int tx = threadIdx.x, ty = threadIdx.y;
    #pragma unroll
    for (int r = ty; r < 32; r += 8)
        s[r][tx] = U[(size_t)(k0 + r) * G3 + j0 + tx];
    __syncthreads();
    #pragma unroll
    for (int r = ty; r < 32; r += 8)
        g_UT[(size_t)(j0 + r) * H + k0 + tx] = s[tx][r];
}

// ---------------- TT stage A ----------------
// P[bt][r(192)][i3i4(64)] = sum_{k=i1i2} v[bt][k][i3i4] * M2[g][k][ocr]
// block: 16 bt, 8 warps; warp covers 2 bt; lane: bt_sub = l>>4, i3i4-quad pq = l&15.
#define TTA_SMEM (32*192*8 + 16*2048*4)   // sM dup 49152 + sV 131072 = 180224
__global__ void __launch_bounds__(256)
ttA_kernel(const float* __restrict__ X) {
    extern __shared__ __align__(16) float smA[];
    float2* sM = (float2*)smA;                 // [k(32)][r(192)] duplicated
    float*  sV = smA + 2*32*192;               // [bt(16)][2048]

    const int tid = threadIdx.x;
    const int bt0 = blockIdx.x * 16;

    for (int i = tid; i < 32*192; i += 256) {
        int k = i / 192, r = i - k*192;
        int g = r >> 6, ocr = r & 63;
        float v = g_M2[g*2048 + k*64 + ocr];
        sM[i] = make_float2(v, v);
    }
    {
        const float4* Xb = (const float4*)(X + (size_t)bt0 * D);
        float4* sv4 = (float4*)sV;
        #pragma unroll 8
        for (int q = 0; q < 32; ++q) sv4[tid + q*256] = Xb[tid + q*256];
    }
    __syncthreads();

    const int wid = tid >> 5, l = tid & 31;
    const int bts = wid*2 + (l >> 4);
    const int pq  = l & 15;
    const float* vb = sV + bts*2048 + pq*4;
    float* Pb = g_P + (size_t)(bt0 + bts) * 12288;

    for (int rp = 0; rp < 12; ++rp) {        // 2 r-groups of 8 per pass
        const int r0 = rp * 16;
        ull acc[16][2];
        #pragma unroll
        for (int r = 0; r < 16; ++r) { acc[r][0] = 0ULL; acc[r][1] = 0ULL; }

        #pragma unroll 4
        for (int k = 0; k < 32; ++k) {
            ulonglong2 vv = *(const ulonglong2*)(vb + k*64);
            const ulonglong2* mrow = (const ulonglong2*)(sM + k*192 + r0);
            #pragma unroll
            for (int m = 0; m < 8; ++m) {
                ulonglong2 mm = mrow[m];
                FMA_F32X2(acc[2*m  ][0], vv.x, mm.x);
                FMA_F32X2(acc[2*m  ][1], vv.y, mm.x);
                FMA_F32X2(acc[2*m+1][0], vv.x, mm.y);
                FMA_F32X2(acc[2*m+1][1], vv.y, mm.y);
            }
        }
        #pragma unroll
        for (int rr = 0; rr < 16; ++rr) {
            int r = r0 + rr;
            int g = r >> 6, o = (r >> 2) & 15, r2 = r & 3;
            float4 out = make_float4(f2lo(acc[rr][0]), f2hi(acc[rr][0]),
                                     f2lo(acc[rr][1]), f2hi(acc[rr][1]));
            *(float4*)(Pb + ((size_t)(g*16 + o))*256 + r2*64 + pq*4) = out;
        }
    }
}

// ---------------- TT stage B ----------------
// per gate g: C[M=BT*16, 64] = P_g[M,256] @ M34g[256,64] + bias -> gi[t][b][3H]
// block tile 256x64, 256 threads, microtile 8Mx8N; A dup'd, B natural pairs.
#define TTB_SMEM (2*16*256*8 + 2*16*64*4)  // 65536 + 8192 = 73728
__global__ void __launch_bounds__(256)
ttB_kernel(const float* __restrict__ bi) {
    extern __shared__ __align__(16) float smB[];
    float2* Asd = (float2*)smB;                 // [2][16][256] dup'd
    float*  Bs  = smB + 2*2*16*256;             // [2][16][64]

    const int tid = threadIdx.x;
    const int g   = blockIdx.y;
    const int m0  = blockIdx.x * 256;
    const int tx  = tid & 7;       // N: cols tx*8..+7
    const int ty  = tid >> 3;      // M: rows ty*8..+7 (ty 0..31)

    const int am = m0 + tid;
    const float* Ap = g_P + ((size_t)(am >> 4) * 48 + g*16 + (am & 15)) * 256;
    const int bk = tid >> 4, bcc = (tid & 15) * 4;
    const float* Bp = g_M34 + (size_t)g * 16384 + bk*64 + bcc;

    ull acc[8][4];
    #pragma unroll
    for (int i = 0; i < 8; ++i)
        #pragma unroll
        for (int n = 0; n < 4; ++n) acc[i][n] = 0ULL;

    float4 a4[4]; float4 b4;
    #pragma unroll
    for (int q = 0; q < 4; ++q) a4[q] = ((const float4*)Ap)[q];
    b4 = *(const float4*)Bp;

    // stage tile 0
    #pragma unroll
    for (int q = 0; q < 4; ++q) {
        Asd[(q*4+0)*256 + tid] = make_float2(a4[q].x, a4[q].x);
        Asd[(q*4+1)*256 + tid] = make_float2(a4[q].y, a4[q].y);
        Asd[(q*4+2)*256 + tid] = make_float2(a4[q].z, a4[q].z);
        Asd[(q*4+3)*256 + tid] = make_float2(a4[q].w, a4[q].w);
    }
    *(float4*)&Bs[bk*64 + bcc] = b4;
    __syncthreads();

    int buf = 0;
    for (int kt = 0; kt < 16; ++kt) {
        if (kt < 15) {
            #pragma unroll
            for (int q = 0; q < 4; ++q)
                a4[q] = ((const float4*)(Ap + (kt+1)*16))[q];
            b4 = *(const float4*)(Bp + (size_t)(kt+1)*16*64);
        }
        #pragma unroll
        for (int k = 0; k < 16; ++k) {
            const ulonglong2* ap = (const ulonglong2*)(Asd + (buf*16 + k)*256 + ty*8);
            ulonglong2 A01 = ap[0], A23 = ap[1], A45 = ap[2], A67 = ap[3];
            const ulonglong2* bp = (const ulonglong2*)(Bs + buf*1024 + k*64 + tx*8);
            ulonglong2 B01 = bp[0], B23 = bp[1];
            FMA_F32X2(acc[0][0], A01.x, B01.x); FMA_F32X2(acc[0][1], A01.x, B01.y);
            FMA_F32X2(acc[0][2], A01.x, B23.x); FMA_F32X2(acc[0][3], A01.x, B23.y);
            FMA_F32X2(acc[1][0], A01.y, B01.x); FMA_F32X2(acc[1][1], A01.y, B01.y);
            FMA_F32X2(acc[1][2], A01.y, B23.x); FMA_F32X2(acc[1][3], A01.y, B23.y);
            FMA_F32X2(acc[2][0], A23.x, B01.x); FMA_F32X2(acc[2][1], A23.x, B01.y);
            FMA_F32X2(acc[2][2], A23.x, B23.x); FMA_F32X2(acc[2][3], A23.x, B23.y);
            FMA_F32X2(acc[3][0], A23.y, B01.x); FMA_F32X2(acc[3][1], A23.y, B01.y);
            FMA_F32X2(acc[3][2], A23.y, B23.x); FMA_F32X2(acc[3][3], A23.y, B23.y);
            FMA_F32X2(acc[4][0], A45.x, B01.x); FMA_F32X2(acc[4][1], A45.x, B01.y);
            FMA_F32X2(acc[4][2], A45.x, B23.x); FMA_F32X2(acc[4][3], A45.x, B23.y);
            FMA_F32X2(acc[5][0], A45.y, B01.x); FMA_F32X2(acc[5][1], A45.y, B01.y);
            FMA_F32X2(acc[5][2], A45.y, B23.x); FMA_F32X2(acc[5][3], A45.y, B23.y);
            FMA_F32X2(acc[6][0], A67.x, B01.x); FMA_F32X2(acc[6][1], A67.x, B01.y);
            FMA_F32X2(acc[6][2], A67.x, B23.x); FMA_F32X2(acc[6][3], A67.x, B23.y);
            FMA_F32X2(acc[7][0], A67.y, B01.x); FMA_F32X2(acc[7][1], A67.y, B01.y);
            FMA_F32X2(acc[7][2], A67.y, B23.x); FMA_F32X2(acc[7][3], A67.y, B23.y);
        }
        if (kt < 15) {
            int nb = buf ^ 1;
            #pragma unroll
            for (int q = 0; q < 4; ++q) {
                Asd[(nb*16 + q*4+0)*256 + tid] = make_float2(a4[q].x, a4[q].x);
                Asd[(nb*16 + q*4+1)*256 + tid] = make_float2(a4[q].y, a4[q].y);
                Asd[(nb*16 + q*4+2)*256 + tid] = make_float2(a4[q].z, a4[q].z);
                Asd[(nb*16 + q*4+3)*256 + tid] = make_float2(a4[q].w, a4[q].w);
            }
            *(float4*)&Bs[nb*1024 + bk*64 + bcc] = b4;
        }
        __syncthreads();
        buf ^= 1;
    }

    // epilogue
    #pragma unroll
    for (int i = 0; i < 8; ++i) {
        int m  = m0 + ty*8 + i;
        int bt = m >> 4, oo = m & 15;
        int bb = bt >> 8, tt = bt & 255;
        const float* bp2 = bi + g*1024 + oo*64 + tx*8;
        float4 o1 = make_float4(f2lo(acc[i][0]) + bp2[0], f2hi(acc[i][0]) + bp2[1],
                                f2lo(acc[i][1]) + bp2[2], f2hi(acc[i][1]) + bp2[3]);
        float4 o2 = make_float4(f2lo(acc[i][2]) + bp2[4], f2hi(acc[i][2]) + bp2[5],
                                f2lo(acc[i][3]) + bp2[6], f2hi(acc[i][3]) + bp2[7]);
        float* dst = g_gi + ((size_t)tt * B + bb) * G3 + g*1024 + oo*64 + tx*8;
        ((float4*)dst)[0] = o1;
        ((float4*)dst)[1] = o2;
    }
}

// ---------------- persistent scan ----------------
// 128 blocks x 256 thr. Warp tile: lane = (bg 0..15, og 0..1); lane owns 4b x 4o x 3g.
// Warps stripe K (8-k blocks, blk8 % 8 == wid). Cross-warp reduce via smem.
#define SCAN_BLOCKS 128
#define US_STRIDE 1028
#define US_SZ (24*US_STRIDE)               // floats: 24672
#define KC 512
#define SH_SZ (64*KC)                      // floats: 32768 (128KB)
#define SCAN_SMEM ((US_SZ + SH_SZ)*4)      // 229760 bytes

__global__ void __launch_bounds__(256, 1)
scan_kernel(const float* __restrict__ bh) {
    extern __shared__ __align__(16) float smem[];
    float* Us = smem;                      // [24][US_STRIDE]
    float* sH = smem + US_SZ;              // [64][512] swizzled; also aliased as red[8][1536]

    const int tid    = threadIdx.x;
    const int wid    = tid >> 5;
    const int l      = tid & 31;
    const int bg     = l & 15;             // batch group (4 batches)
    const int og     = l >> 4;             // o group (4 outputs)
    const int swz    = bg & 7;
    const int blk_o0 = blockIdx.x * 8;

    // stage U rows: row = g*8 + o_local
    for (int i = tid; i < 24*1024; i += 256) {
        int r = i >> 10, k = i & 1023;
        Us[r*US_STRIDE + k] = g_UT[(size_t)((r >> 3)*H + blk_o0 + (r & 7))*H + k];
    }

    // per-thread GRU output mapping: 2 (b,o) pairs
    int pb[2], po[2];
    float bhv[2][3];
    #pragma unroll
    for (int e = 0; e < 2; ++e) {
        int p = tid*2 + e;
        pb[e] = p >> 3;
        po[e] = blk_o0 + (p & 7);
        bhv[e][0] = bh[po[e]];
        bhv[e][1] = bh[H + po[e]];
        bhv[e][2] = bh[2*H + po[e]];
    }

    const float* wbase = Us + og*4*US_STRIDE;

    for (int t = 0; t < T; ++t) {
        const float* hc = g_h[t & 1];
        float*       hn = g_h[(t & 1) ^ 1];

        // prefetch gi + h_old for this thread's outputs
        float giv[2][3], hold[2];
        #pragma unroll
        for (int e = 0; e < 2; ++e) {
            const float* gp = g_gi + ((size_t)t * B + pb[e]) * G3 + po[e];
            giv[e][0] = __ldg(gp);
            giv[e][1] = __ldg(gp + H);
            giv[e][2] = __ldg(gp + 2*H);
            hold[e]   = __ldcg(hc + pb[e]*H + po[e]);
        }

        ull acc[48];
        #pragma unroll
        for (int i = 0; i < 48; ++i) acc[i] = 0ULL;

        #pragma unroll
        for (int c = 0; c < 2; ++c) {
            const int kc = c * KC;
            __syncthreads();   // previous use of sH (compute or red) done
            // stage h chunk, XOR-swizzled 16B units, via L2
            #pragma unroll 8
            for (int q = 0; q < 32; ++q) {
                int f = tid + q*256;             // float4 index 0..8191
                int b = f >> 7, cc = f & 127;
                int cs = (cc & ~7) | ((cc & 7) ^ ((b >> 2) & 7));
                float4 v = __ldcg(((const float4*)(hc + (size_t)b*H + kc)) + cc);
                *(float4*)(sH + b*KC + cs*4) = v;
            }
            __syncthreads();

            for (int jr = 0; jr < 8; ++jr) {
                const int blk8 = wid + 8*jr;     // 8-k block within chunk
                #pragma unroll
                for (int half = 0; half < 2; ++half) {
                    const int ci  = blk8*2 + half;            // 16B chunk idx
                    const int cis = (ci & ~7) | ((ci & 7) ^ swz);
                    const float* hp = sH + cis*4;
                    ulonglong2 hv0 = *(const ulonglong2*)(hp + (bg*4+0)*KC);
                    ulonglong2 hv1 = *(const ulonglong2*)(hp + (bg*4+1)*KC);
                    ulonglong2 hv2 = *(const ulonglong2*)(hp + (bg*4+2)*KC);
                    ulonglong2 hv3 = *(const ulonglong2*)(hp + (bg*4+3)*KC);
                    const int lkh = blk8*8 + half*4 + kc;     // global k
                    #pragma unroll
                    for (int g = 0; g < 3; ++g) {
                        const float* wb = wbase + (size_t)g*8*US_STRIDE + lkh;
                        ulonglong2 w0 = *(const ulonglong2*)(wb);
                        ulonglong2 w1 = *(const ulonglong2*)(wb + US_STRIDE);
                        ulonglong2 w2 = *(const ulonglong2*)(wb + 2*US_STRIDE);
                        ulonglong2 w3 = *(const ulonglong2*)(wb + 3*US_STRIDE);
                        ull* ag = acc + g*16;
                        FMA_F32X2(ag[ 0], hv0.x, w0.x); FMA_F32X2(ag[ 0], hv0.y, w0.y);
                        FMA_F32X2(ag[ 1], hv1.x, w0.x); FMA_F32X2(ag[ 1], hv1.y, w0.y);
                        FMA_F32X2(ag[ 2], hv2.x, w0.x); FMA_F32X2(ag[ 2], hv2.y, w0.y);
                        FMA_F32X2(ag[ 3], hv3.x, w0.x); FMA_F32X2(ag[ 3], hv3.y, w0.y);
                        FMA_F32X2(ag[ 4], hv0.x, w1.x); FMA_F32X2(ag[ 4], hv0.y, w1.y);
                        FMA_F32X2(ag[ 5], hv1.x, w1.x); FMA_F32X2(ag[ 5], hv1.y, w1.y);
                        FMA_F32X2(ag[ 6], hv2.x, w1.x); FMA_F32X2(ag[ 6], hv2.y, w1.y);
                        FMA_F32X2(ag[ 7], hv3.x, w1.x); FMA_F32X2(ag[ 7], hv3.y, w1.y);
                        FMA_F32X2(ag[ 8], hv0.x, w2.x); FMA_F32X2(ag[ 8], hv0.y, w2.y);
                        FMA_F32X2(ag[ 9], hv1.x, w2.x); FMA_F32X2(ag[ 9], hv1.y, w2.y);
                        FMA_F32X2(ag[10], hv2.x, w2.x); FMA_F32X2(ag[10], hv2.y, w2.y);
                        FMA_F32X2(ag[11], hv3.x, w2.x); FMA_F32X2(ag[11], hv3.y, w2.y);
                        FMA_F32X2(ag[12], hv0.x, w3.x); FMA_F32X2(ag[12], hv0.y, w3.y);
                        FMA_F32X2(ag[13], hv1.x, w3.x); FMA_F32X2(ag[13], hv1.y, w3.y);
                        FMA_F32X2(ag[14], hv2.x, w3.x); FMA_F32X2(ag[14], hv2.y, w3.y);
                        FMA_F32X2(ag[15], hv3.x, w3.x); FMA_F32X2(ag[15], hv3.y, w3.y);
                    }
                }
            }
        }

        // cross-warp reduction through smem (aliases sH)
        __syncthreads();
        float* red = sH;
        #pragma unroll
        for (int g = 0; g < 3; ++g)
            #pragma unroll
            for (int j = 0; j < 4; ++j)
                #pragma unroll
                for (int i = 0; i < 4; ++i) {
                    ull a = acc[g*16 + j*4 + i];
                    red[wid*1536 + g*512 + (bg*4+i)*8 + og*4 + j] = f2lo(a) + f2hi(a);
                }
        __syncthreads();

        #pragma unroll
        for (int e = 0; e < 2; ++e) {
            int p = tid*2 + e;
            int b = p >> 3, ol = p & 7;
            float s0 = 0.f, s1 = 0.f, s2 = 0.f;
            #pragma unroll
            for (int w = 0; w < 8; ++w) {
                s0 += red[w*1536 +         b*8 + ol];
                s1 += red[w*1536 +  512 +  b*8 + ol];
                s2 += red[w*1536 + 1024 +  b*8 + ol];
            }
            float r = 1.f / (1.f + expf(-(giv[e][0] + s0 + bhv[e][0])));
            float z = 1.f / (1.f + expf(-(giv[e][1] + s1 + bhv[e][1])));
            float n = tanhf(giv[e][2] + r * (s2 + bhv[e][2]));
            hn[pb[e]*H + po[e]] = (1.f - z) * n + z * hold[e];
        }

        // grid barrier: release/acquire at L2, monotone counters
        __syncthreads();
        if (tid == 0) {
            unsigned old;
            asm volatile("atom.add.release.gpu.u32 %0, [%1], 1;"
                         : "=r"(old) : "l"(&g_barc) : "memory");
            unsigned tgt = (unsigned)(t + 1);
            if (old == tgt * SCAN_BLOCKS - 1u) {
                asm volatile("st.release.gpu.u32 [%0], %1;" :: "l"(&g_barg), "r"(tgt) : "memory");
            } else {
                unsigned cur;
                do {
                    asm volatile("ld.acquire.gpu.u32 %0, [%1];" : "=r"(cur) : "l"(&g_barg) : "memory");
                } while (cur < tgt);
            }
        }
        __syncthreads();
    }
}

// ---------------- final FC + ReLU ----------------
__global__ void fc_kernel(const float* __restrict__ Wfc,
                          const float* __restrict__ bfc,
                          float* __restrict__ out) {
    int idx = blockIdx.x * blockDim.x + threadIdx.x;
    if (idx >= B * NC) return;
    int b = idx / NC, c = idx - b * NC;
    const float* h = g_h[0] + (size_t)b * H;   // T even -> final state in buffer 0
    float s0 = bfc[c], s1 = 0.f, s2 = 0.f, s3 = 0.f;
    #pragma unroll 4
    for (int k = 0; k < H; k += 4) {
        float4 hv = *(const float4*)(h + k);
        s0 += hv.x * Wfc[(size_t)(k    ) * NC + c];
        s1 += hv.y * Wfc[(size_t)(k + 1) * NC + c];
        s2 += hv.z * Wfc[(size_t)(k + 2) * NC + c];
        s3 += hv.w * Wfc[(size_t)(k + 3) * NC + c];
    }
    out[idx] = fmaxf((s0 + s1) + (s2 + s3), 0.f);
}

// ---------------- launcher ----------------
extern "C" void kernel_launch(void* const* d_in, const int* in_sizes, int n_in,
                              void* d_out, int out_size) {
    (void)in_sizes; (void)n_in; (void)out_size;
    const float* x    = (const float*)d_in[0];
    const float* c0   = (const float*)d_in[1];
    const float* c1   = (const float*)d_in[2];
    const float* c2   = (const float*)d_in[3];
    const float* c3   = (const float*)d_in[4];
    const float* bi   = (const float*)d_in[5];
    const float* U    = (const float*)d_in[6];
    const float* bh   = (const float*)d_in[7];
    const float* Wfc  = (const float*)d_in[8];
    const float* bfc  = (const float*)d_in[9];

    cudaFuncSetAttribute(ttA_kernel,  cudaFuncAttributeMaxDynamicSharedMemorySize, TTA_SMEM);
    cudaFuncSetAttribute(ttB_kernel,  cudaFuncAttributeMaxDynamicSharedMemorySize, TTB_SMEM);
    cudaFuncSetAttribute(scan_kernel, cudaFuncAttributeMaxDynamicSharedMemorySize, SCAN_SMEM);

    init_kernel<<<64, 256>>>();
    build_M_kernel<<<1, 256>>>(c0, c1, c2, c3);
    build_UT_kernel<<<dim3(96, 32), dim3(32, 8)>>>(U);
    ttA_kernel<<<BT/16, 256, TTA_SMEM>>>(x);
    ttB_kernel<<<dim3(BT*16/256, 3), 256, TTB_SMEM>>>(bi);
    scan_kernel<<<SCAN_BLOCKS, 256, SCAN_SMEM>>>(bh);
    fc_kernel<<<(B * NC + 255) / 256, 256>>>(Wfc, bfc, (float*)d_out);
}

// round 7
// speedup vs baseline: 1.4408x; 1.0905x over previous
#include <cuda_runtime.h>
#include <cuda_fp16.h>
#include <math.h>
#include <stdint.h>

typedef unsigned long long ull;

// ---------------- problem constants ----------------
#define B   64
#define T   256
#define D   2048
#define H   1024
#define G3  3072
#define NC  1000
#define BT  (B*T)

#define FMA_F32X2(acc, a, b) \
    asm("fma.rn.f32x2 %0, %1, %2, %0;" : "+l"(acc) : "l"(a), "l"(b))

#define CP_ASYNC16(dst, src) \
    asm volatile("cp.async.cg.shared.global [%0], [%1], 16;" :: "r"(dst), "l"(src))
#define CP_COMMIT() asm volatile("cp.async.commit_group;")
#define CP_WAIT(n)  asm volatile("cp.async.wait_group %0;" :: "n"(n))

__device__ __forceinline__ float f2lo(ull v) { return __uint_as_float((unsigned)(v & 0xffffffffULL)); }
__device__ __forceinline__ float f2hi(ull v) { return __uint_as_float((unsigned)(v >> 32)); }

// ---------------- device scratch ----------------
__device__ __align__(16) float  g_M2 [3*2048];            // [g][i1i2(32)][o1o2r2(64)]
__device__ __align__(16) float  g_M34[3*16384];           // [g][k(256)][64]
__device__ __align__(16) float  g_UT [(size_t)G3*H];      // U^T: [j][k]
__device__ __align__(16) __half g_P  [(size_t)BT*12288];  // [bt][g][o1o2][r2*64+i3i4] fp16
__device__ __align__(16) float  g_gi [(size_t)BT*G3];     // [t][b][3H]
__device__ __align__(16) float  g_h  [2][B*H];            // ping-pong hidden [b][k]
__device__ unsigned g_barc;
__device__ unsigned g_barg;

// ---------------- init ----------------
__global__ void init_kernel() {
    int idx = blockIdx.x * blockDim.x + threadIdx.x;
    for (int i = idx; i < B*H; i += gridDim.x * blockDim.x) g_h[0][i] = 0.f;
    if (idx == 0) { g_barc = 0u; g_barg = 0u; }
}

// ---------------- build M2, M34 from TT cores ----------------
__global__ void build_M_kernel(const float* __restrict__ c0,
                               const float* __restrict__ c1,
                               const float* __restrict__ c2,
                               const float* __restrict__ c3) {
    for (int idx = threadIdx.x; idx < 3*2048; idx += blockDim.x) {
        int r2 = idx & 3, o2 = (idx>>2)&3, o1 = (idx>>4)&3;
        int i2 = (idx>>6)&7, i1 = (idx>>9)&3, g = idx>>11;
        float s = 0.f;
        #pragma unroll
        for (int r1 = 0; r1 < 4; ++r1)
            s += c0[g*64 + i1*16 + o1*4 + r1] *
                 c1[g*512 + r1*128 + i2*16 + o2*4 + r2];
        g_M2[idx] = s;
    }
    for (int idx = threadIdx.x; idx < 3*16384; idx += blockDim.x) {
        int o4 = idx & 7, o3 = (idx>>3)&7, i4 = (idx>>6)&7;
        int i3 = (idx>>9)&7, r2 = (idx>>12)&3, g = idx>>14;
        float s = 0.f;
        #pragma unroll
        for (int r3 = 0; r3 < 4; ++r3)
            s += c2[g*1024 + r2*256 + i3*32 + o3*4 + r3] *
                 c3[g*256  + r3*64  + i4*8  + o4];
        g_M34[idx] = s;
    }
}

// ---------------- transpose U [H,G3] -> UT [G3,H] ----------------
__global__ void build_UT_kernel(const float* __restrict__ U) {
    __shared__ float s[32][33];
    int j0 = blockIdx.x * 32;
    int k0 = blockIdx.y * 32;
    int tx = threadIdx.x, ty = threadIdx.y;
    #pragma unroll
    for (int r = ty; r < 32; r += 8)
        s[r][tx] = U[(size_t)(k0 + r) * G3 + j0 + tx];
    __syncthreads();
    #pragma unroll
    for (int r = ty; r < 32; r += 8)
        g_UT[(size_t)(j0 + r) * H + k0 + tx] = s[tx][r];
}

// ---------------- TT stage A ----------------
#define TTA_SMEM (32*192*8 + 16*2048*4)   // 180224
__global__ void __launch_bounds__(256)
ttA_kernel(const float* __restrict__ X) {
    extern __shared__ __align__(16) float smA[];
    float2* sM = (float2*)smA;                 // [k(32)][r(192)] duplicated
    float*  sV = smA + 2*32*192;               // [bt(16)][2048]

    const int tid = threadIdx.x;
    const int bt0 = blockIdx.x * 16;

    for (int i = tid; i < 32*192; i += 256) {
        int k = i / 192, r = i - k*192;
        int g = r >> 6, ocr = r & 63;
        float v = g_M2[g*2048 + k*64 + ocr];
        sM[i] = make_float2(v, v);
    }
    {
        const float4* Xb = (const float4*)(X + (size_t)bt0 * D);
        float4* sv4 = (float4*)sV;
        #pragma unroll 8
        for (int q = 0; q < 32; ++q) sv4[tid + q*256] = Xb[tid + q*256];
    }
    __syncthreads();

    const int wid = tid >> 5, l = tid & 31;
    const int bts = wid*2 + (l >> 4);
    const int pq  = l & 15;
    const float* vb = sV + bts*2048 + pq*4;
    __half* Pb = g_P + (size_t)(bt0 + bts) * 12288;

    for (int rp = 0; rp < 12; ++rp) {
        const int r0 = rp * 16;
        ull acc[16][2];
        #pragma unroll
        for (int r = 0; r < 16; ++r) { acc[r][0] = 0ULL; acc[r][1] = 0ULL; }

        #pragma unroll 4
        for (int k = 0; k < 32; ++k) {
            ulonglong2 vv = *(const ulonglong2*)(vb + k*64);
            const ulonglong2* mrow = (const ulonglong2*)(sM + k*192 + r0);
            #pragma unroll
            for (int m = 0; m < 8; ++m) {
                ulonglong2 mm = mrow[m];
                FMA_F32X2(acc[2*m  ][0], vv.x, mm.x);
                FMA_F32X2(acc[2*m  ][1], vv.y, mm.x);
                FMA_F32X2(acc[2*m+1][0], vv.x, mm.y);
                FMA_F32X2(acc[2*m+1][1], vv.y, mm.y);
            }
        }
        #pragma unroll
        for (int rr = 0; rr < 16; ++rr) {
            int r = r0 + rr;
            int g = r >> 6, o = (r >> 2) & 15, r2 = r & 3;
            __half2 hA = __floats2half2_rn(f2lo(acc[rr][0]), f2hi(acc[rr][0]));
            __half2 hB = __floats2half2_rn(f2lo(acc[rr][1]), f2hi(acc[rr][1]));
            __half2* d2 = (__half2*)(Pb + ((size_t)(g*16 + o))*256 + r2*64 + pq*4);
            d2[0] = hA; d2[1] = hB;
        }
    }
}

// ---------------- TT stage B ----------------
#define TTB_SMEM (2*16*256*8 + 2*16*64*4)  // 73728
__device__ __forceinline__ void ttb_stageA(float2* Asd, int base, int tid,
                                           uint4 a0, uint4 a1) {
    const __half2* h0 = (const __half2*)&a0;
    const __half2* h1 = (const __half2*)&a1;
    #pragma unroll
    for (int q = 0; q < 4; ++q) {
        float2 f = __half22float2(h0[q]);
        Asd[(base + 2*q    )*256 + tid] = make_float2(f.x, f.x);
        Asd[(base + 2*q + 1)*256 + tid] = make_float2(f.y, f.y);
    }
    #pragma unroll
    for (int q = 0; q < 4; ++q) {
        float2 f = __half22float2(h1[q]);
        Asd[(base + 8 + 2*q    )*256 + tid] = make_float2(f.x, f.x);
        Asd[(base + 8 + 2*q + 1)*256 + tid] = make_float2(f.y, f.y);
    }
}

__global__ void __launch_bounds__(256)
ttB_kernel(const float* __restrict__ bi) {
    extern __shared__ __align__(16) float smB[];
    float2* Asd = (float2*)smB;                 // [2][16][256] dup'd
    float*  Bs  = smB + 2*2*16*256;             // [2][16][64]

    const int tid = threadIdx.x;
    const int g   = blockIdx.y;
    const int m0  = blockIdx.x * 256;
    const int tx  = tid & 7;
    const int ty  = tid >> 3;

    const int am = m0 + tid;
    const __half* Ap = g_P + ((size_t)(am >> 4) * 48 + g*16 + (am & 15)) * 256;
    const int bk = tid >> 4, bcc = (tid & 15) * 4;
    const float* Bp = g_M34 + (size_t)g * 16384 + bk*64 + bcc;

    ull acc[8][4];
    #pragma unroll
    for (int i = 0; i < 8; ++i)
        #pragma unroll
        for (int n = 0; n < 4; ++n) acc[i][n] = 0ULL;

    uint4 a0 = *(const uint4*)(Ap);
    uint4 a1 = *(const uint4*)(Ap + 8);
    float4 b4 = *(const float4*)Bp;

    ttb_stageA(Asd, 0, tid, a0, a1);
    *(float4*)&Bs[bk*64 + bcc] = b4;
    __syncthreads();

    int buf = 0;
    for (int kt = 0; kt < 16; ++kt) {
        if (kt < 15) {
            a0 = *(const uint4*)(Ap + (kt+1)*16);
            a1 = *(const uint4*)(Ap + (kt+1)*16 + 8);
            b4 = *(const float4*)(Bp + (size_t)(kt+1)*16*64);
        }
        #pragma unroll
        for (int k = 0; k < 16; ++k) {
            const ulonglong2* ap = (const ulonglong2*)(Asd + (buf*16 + k)*256 + ty*8);
            ulonglong2 A01 = ap[0], A23 = ap[1], A45 = ap[2], A67 = ap[3];
            const ulonglong2* bp = (const ulonglong2*)(Bs + buf*1024 + k*64 + tx*8);
            ulonglong2 B01 = bp[0], B23 = bp[1];
            FMA_F32X2(acc[0][0], A01.x, B01.x); FMA_F32X2(acc[0][1], A01.x, B01.y);
            FMA_F32X2(acc[0][2], A01.x, B23.x); FMA_F32X2(acc[0][3], A01.x, B23.y);
            FMA_F32X2(acc[1][0], A01.y, B01.x); FMA_F32X2(acc[1][1], A01.y, B01.y);
            FMA_F32X2(acc[1][2], A01.y, B23.x); FMA_F32X2(acc[1][3], A01.y, B23.y);
            FMA_F32X2(acc[2][0], A23.x, B01.x); FMA_F32X2(acc[2][1], A23.x, B01.y);
            FMA_F32X2(acc[2][2], A23.x, B23.x); FMA_F32X2(acc[2][3], A23.x, B23.y);
            FMA_F32X2(acc[3][0], A23.y, B01.x); FMA_F32X2(acc[3][1], A23.y, B01.y);
            FMA_F32X2(acc[3][2], A23.y, B23.x); FMA_F32X2(acc[3][3], A23.y, B23.y);
            FMA_F32X2(acc[4][0], A45.x, B01.x); FMA_F32X2(acc[4][1], A45.x, B01.y);
            FMA_F32X2(acc[4][2], A45.x, B23.x); FMA_F32X2(acc[4][3], A45.x, B23.y);
            FMA_F32X2(acc[5][0], A45.y, B01.x); FMA_F32X2(acc[5][1], A45.y, B01.y);
            FMA_F32X2(acc[5][2], A45.y, B23.x); FMA_F32X2(acc[5][3], A45.y, B23.y);
            FMA_F32X2(acc[6][0], A67.x, B01.x); FMA_F32X2(acc[6][1], A67.x, B01.y);
            FMA_F32X2(acc[6][2], A67.x, B23.x); FMA_F32X2(acc[6][3], A67.x, B23.y);
            FMA_F32X2(acc[7][0], A67.y, B01.x); FMA_F32X2(acc[7][1], A67.y, B01.y);
            FMA_F32X2(acc[7][2], A67.y, B23.x); FMA_F32X2(acc[7][3], A67.y, B23.y);
        }
        if (kt < 15) {
            int nb = buf ^ 1;
            ttb_stageA(Asd, nb*16, tid, a0, a1);
            *(float4*)&Bs[nb*1024 + bk*64 + bcc] = b4;
        }
        __syncthreads();
        buf ^= 1;
    }

    #pragma unroll
    for (int i = 0; i < 8; ++i) {
        int m  = m0 + ty*8 + i;
        int bt = m >> 4, oo = m & 15;
        int bb = bt >> 8, tt = bt & 255;
        const float* bp2 = bi + g*1024 + oo*64 + tx*8;
        float4 o1 = make_float4(f2lo(acc[i][0]) + bp2[0], f2hi(acc[i][0]) + bp2[1],
                                f2lo(acc[i][1]) + bp2[2], f2hi(acc[i][1]) + bp2[3]);
        float4 o2 = make_float4(f2lo(acc[i][2]) + bp2[4], f2hi(acc[i][2]) + bp2[5],
                                f2lo(acc[i][3]) + bp2[6], f2hi(acc[i][3]) + bp2[7]);
        float* dst = g_gi + ((size_t)tt * B + bb) * G3 + g*1024 + oo*64 + tx*8;
        ((float4*)dst)[0] = o1;
        ((float4*)dst)[1] = o2;
    }
}

// ---------------- persistent scan ----------------
// 128 blocks x 256 thr; lane = (bg 0..15, og 0..1); lane tile 4b x 4o x 3g.
// Warps stripe K; 4 chunks of 256 k, cp.async double-buffered h staging.
#define SCAN_BLOCKS 128
#define US_STRIDE 1028
#define US_SZ (24*US_STRIDE)               // 24672 floats
#define KCC 256
#define SHBUF (64*KCC)                     // 16384 floats per buffer
#define SCAN_SMEM ((US_SZ + 2*SHBUF)*4)    // 98688 + 131072 = 229760 B

__global__ void __launch_bounds__(256, 1)
scan_kernel(const float* __restrict__ bh) {
    extern __shared__ __align__(16) float smem[];
    float* Us = smem;                      // [24][US_STRIDE]
    float* sH = smem + US_SZ;              // 2 x [64][256]; buf0 aliased as red[8][1536]

    const int tid    = threadIdx.x;
    const int wid    = tid >> 5;
    const int l      = tid & 31;
    const int bg     = l & 15;
    const int og     = l >> 4;
    const int swz    = bg & 7;
    const int blk_o0 = blockIdx.x * 8;

    for (int i = tid; i < 24*1024; i += 256) {
        int r = i >> 10, k = i & 1023;
        Us[r*US_STRIDE + k] = g_UT[(size_t)((r >> 3)*H + blk_o0 + (r & 7))*H + k];
    }

    int pb[2], po[2];
    float bhv[2][3];
    #pragma unroll
    for (int e = 0; e < 2; ++e) {
        int p = tid*2 + e;
        pb[e] = p >> 3;
        po[e] = blk_o0 + (p & 7);
        bhv[e][0] = bh[po[e]];
        bhv[e][1] = bh[H + po[e]];
        bhv[e][2] = bh[2*H + po[e]];
    }

    const float* wbase = Us + og*4*US_STRIDE;
    const unsigned sh_base = (unsigned)__cvta_generic_to_shared(sH);

    // per-thread staging map (16 x 16B per chunk)
    int st_b[16], st_cs[16];
    #pragma unroll
    for (int q = 0; q < 16; ++q) {
        int f = tid + q*256;               // float4 index 0..4095
        int b = f >> 6, cc = f & 63;
        st_b[q]  = b;
        st_cs[q] = (cc & ~7) | ((cc & 7) ^ ((b >> 2) & 7));
    }

    for (int t = 0; t < T; ++t) {
        const float* hc = g_h[t & 1];
        float*       hn = g_h[(t & 1) ^ 1];

        // stage chunk 0 (async)
        #pragma unroll
        for (int q = 0; q < 16; ++q) {
            const float* src = hc + (size_t)st_b[q]*H + ((tid + q*256) & 63)*4;
            unsigned dst = sh_base + (unsigned)((st_b[q]*KCC + st_cs[q]*4) * 4);
            CP_ASYNC16(dst, src);
        }
        CP_COMMIT();

        // prefetch gi + h_old
        float giv[2][3], hold[2];
        #pragma unroll
        for (int e = 0; e < 2; ++e) {
            const float* gp = g_gi + ((size_t)t * B + pb[e]) * G3 + po[e];
            giv[e][0] = __ldg(gp);
            giv[e][1] = __ldg(gp + H);
            giv[e][2] = __ldg(gp + 2*H);
            hold[e]   = __ldcg(hc + pb[e]*H + po[e]);
        }

        ull acc[48];
        #pragma unroll
        for (int i = 0; i < 48; ++i) acc[i] = 0ULL;

        #pragma unroll
        for (int c = 0; c < 4; ++c) {
            if (c < 3) {
                const int cn = c + 1;
                const unsigned bofs = (unsigned)(((cn & 1)*SHBUF) * 4);
                #pragma unroll
                for (int q = 0; q < 16; ++q) {
                    const float* src = hc + (size_t)st_b[q]*H + cn*KCC + ((tid + q*256) & 63)*4;
                    unsigned dst = sh_base + bofs + (unsigned)((st_b[q]*KCC + st_cs[q]*4) * 4);
                    CP_ASYNC16(dst, src);
                }
                CP_COMMIT();
                CP_WAIT(1);
            } else {
                CP_WAIT(0);
            }
            __syncthreads();

            const float* hbuf = sH + (c & 1)*SHBUF;
            const int kc = c * KCC;

            for (int jr = 0; jr < 4; ++jr) {
                const int blk8 = wid + 8*jr;
                #pragma unroll
                for (int half = 0; half < 2; ++half) {
                    const int ci  = blk8*2 + half;
                    const int cis = (ci & ~7) | ((ci & 7) ^ swz);
                    const float* hp = hbuf + cis*4;
                    ulonglong2 hv0 = *(const ulonglong2*)(hp + (bg*4+0)*KCC);
                    ulonglong2 hv1 = *(const ulonglong2*)(hp + (bg*4+1)*KCC);
                    ulonglong2 hv2 = *(const ulonglong2*)(hp + (bg*4+2)*KCC);
                    ulonglong2 hv3 = *(const ulonglong2*)(hp + (bg*4+3)*KCC);
                    const int lkh = kc + blk8*8 + half*4;
                    #pragma unroll
                    for (int g = 0; g < 3; ++g) {
                        const float* wb = wbase + (size_t)g*8*US_STRIDE + lkh;
                        ulonglong2 w0 = *(const ulonglong2*)(wb);
                        ulonglong2 w1 = *(const ulonglong2*)(wb + US_STRIDE);
                        ulonglong2 w2 = *(const ulonglong2*)(wb + 2*US_STRIDE);
                        ulonglong2 w3 = *(const ulonglong2*)(wb + 3*US_STRIDE);
                        ull* ag = acc + g*16;
                        FMA_F32X2(ag[ 0], hv0.x, w0.x); FMA_F32X2(ag[ 0], hv0.y, w0.y);
                        FMA_F32X2(ag[ 1], hv1.x, w0.x); FMA_F32X2(ag[ 1], hv1.y, w0.y);
                        FMA_F32X2(ag[ 2], hv2.x, w0.x); FMA_F32X2(ag[ 2], hv2.y, w0.y);
                        FMA_F32X2(ag[ 3], hv3.x, w0.x); FMA_F32X2(ag[ 3], hv3.y, w0.y);
                        FMA_F32X2(ag[ 4], hv0.x, w1.x); FMA_F32X2(ag[ 4], hv0.y, w1.y);
                        FMA_F32X2(ag[ 5], hv1.x, w1.x); FMA_F32X2(ag[ 5], hv1.y, w1.y);
                        FMA_F32X2(ag[ 6], hv2.x, w1.x); FMA_F32X2(ag[ 6], hv2.y, w1.y);
                        FMA_F32X2(ag[ 7], hv3.x, w1.x); FMA_F32X2(ag[ 7], hv3.y, w1.y);
                        FMA_F32X2(ag[ 8], hv0.x, w2.x); FMA_F32X2(ag[ 8], hv0.y, w2.y);
                        FMA_F32X2(ag[ 9], hv1.x, w2.x); FMA_F32X2(ag[ 9], hv1.y, w2.y);
                        FMA_F32X2(ag[10], hv2.x, w2.x); FMA_F32X2(ag[10], hv2.y, w2.y);
                        FMA_F32X2(ag[11], hv3.x, w2.x); FMA_F32X2(ag[11], hv3.y, w2.y);
                        FMA_F32X2(ag[12], hv0.x, w3.x); FMA_F32X2(ag[12], hv0.y, w3.y);
                        FMA_F32X2(ag[13], hv1.x, w3.x); FMA_F32X2(ag[13], hv1.y, w3.y);
                        FMA_F32X2(ag[14], hv2.x, w3.x); FMA_F32X2(ag[14], hv2.y, w3.y);
                        FMA_F32X2(ag[15], hv3.x, w3.x); FMA_F32X2(ag[15], hv3.y, w3.y);
                    }
                }
            }
            __syncthreads();
        }

        // cross-warp reduction through smem (aliases sH buffer 0)
        float* red = sH;
        #pragma unroll
        for (int g = 0; g < 3; ++g)
            #pragma unroll
            for (int j = 0; j < 4; ++j)
                #pragma unroll
                for (int i = 0; i < 4; ++i) {
                    ull a = acc[g*16 + j*4 + i];
                    red[wid*1536 + g*512 + (bg*4+i)*8 + og*4 + j] = f2lo(a) + f2hi(a);
                }
        __syncthreads();

        #pragma unroll
        for (int e = 0; e < 2; ++e) {
            int p = tid*2 + e;
            int b = p >> 3, ol = p & 7;
            float s0 = 0.f, s1 = 0.f, s2 = 0.f;
            #pragma unroll
            for (int w = 0; w < 8; ++w) {
                s0 += red[w*1536 +         b*8 + ol];
                s1 += red[w*1536 +  512 +  b*8 + ol];
                s2 += red[w*1536 + 1024 +  b*8 + ol];
            }
            float r  = 1.f / (1.f + __expf(-(giv[e][0] + s0 + bhv[e][0])));
            float z  = 1.f / (1.f + __expf(-(giv[e][1] + s1 + bhv[e][1])));
            float na = giv[e][2] + r * (s2 + bhv[e][2]);
            float te = __expf(2.f * na);
            float n  = 1.f - 2.f / (te + 1.f);
            hn[pb[e]*H + po[e]] = (1.f - z) * n + z * hold[e];
        }

        // grid barrier: release/acquire at L2, monotone counters
        __syncthreads();
        if (tid == 0) {
            unsigned old;
            asm volatile("atom.add.release.gpu.u32 %0, [%1], 1;"
                         : "=r"(old) : "l"(&g_barc) : "memory");
            unsigned tgt = (unsigned)(t + 1);
            if (old == tgt * SCAN_BLOCKS - 1u) {
                asm volatile("st.release.gpu.u32 [%0], %1;" :: "l"(&g_barg), "r"(tgt) : "memory");
            } else {
                unsigned cur;
                do {
                    asm volatile("ld.acquire.gpu.u32 %0, [%1];" : "=r"(cur) : "l"(&g_barg) : "memory");
                } while (cur < tgt);
            }
        }
        __syncthreads();
    }
}

// ---------------- final FC + ReLU ----------------
__global__ void fc_kernel(const float* __restrict__ Wfc,
                          const float* __restrict__ bfc,
                          float* __restrict__ out) {
    int idx = blockIdx.x * blockDim.x + threadIdx.x;
    if (idx >= B * NC) return;
    int b = idx / NC, c = idx - b * NC;
    const float* h = g_h[0] + (size_t)b * H;   // T even -> final state in buffer 0
    float s0 = bfc[c], s1 = 0.f, s2 = 0.f, s3 = 0.f;
    #pragma unroll 4
    for (int k = 0; k < H; k += 4) {
        float4 hv = *(const float4*)(h + k);
        s0 += hv.x * Wfc[(size_t)(k    ) * NC + c];
        s1 += hv.y * Wfc[(size_t)(k + 1) * NC + c];
        s2 += hv.z * Wfc[(size_t)(k + 2) * NC + c];
        s3 += hv.w * Wfc[(size_t)(k + 3) * NC + c];
    }
    out[idx] = fmaxf((s0 + s1) + (s2 + s3), 0.f);
}

// ---------------- launcher ----------------
extern "C" void kernel_launch(void* const* d_in, const int* in_sizes, int n_in,
                              void* d_out, int out_size) {
    (void)in_sizes; (void)n_in; (void)out_size;
    const float* x    = (const float*)d_in[0];
    const float* c0   = (const float*)d_in[1];
    const float* c1   = (const float*)d_in[2];
    const float* c2   = (const float*)d_in[3];
    const float* c3   = (const float*)d_in[4];
    const float* bi   = (const float*)d_in[5];
    const float* U    = (const float*)d_in[6];
    const float* bh   = (const float*)d_in[7];
    const float* Wfc  = (const float*)d_in[8];
    const float* bfc  = (const float*)d_in[9];

    cudaFuncSetAttribute(ttA_kernel,  cudaFuncAttributeMaxDynamicSharedMemorySize, TTA_SMEM);
    cudaFuncSetAttribute(ttB_kernel,  cudaFuncAttributeMaxDynamicSharedMemorySize, TTB_SMEM);
    cudaFuncSetAttribute(scan_kernel, cudaFuncAttributeMaxDynamicSharedMemorySize, SCAN_SMEM);

    init_kernel<<<64, 256>>>();
    build_M_kernel<<<1, 256>>>(c0, c1, c2, c3);
    build_UT_kernel<<<dim3(96, 32), dim3(32, 8)>>>(U);
    ttA_kernel<<<BT/16, 256, TTA_SMEM>>>(x);
    ttB_kernel<<<dim3(BT*16/256, 3), 256, TTB_SMEM>>>(bi);
    scan_kernel<<<SCAN_BLOCKS, 256, SCAN_SMEM>>>(bh);
    fc_kernel<<<(B * NC + 255) / 256, 256>>>(Wfc, bfc, (float*)d_out);
}

// round 9
// speedup vs baseline: 2.1377x; 1.4837x over previous
#include <cuda_runtime.h>
#include <cuda_fp16.h>
#include <cuda_bf16.h>
#include <math.h>
#include <stdint.h>

typedef unsigned long long ull;

// ---------------- problem constants ----------------
#define B   64
#define T   256
#define D   2048
#define H   1024
#define G3  3072
#define NC  1000
#define BT  (B*T)

#define FMA_F32X2(acc, a, b) \
    asm("fma.rn.f32x2 %0, %1, %2, %0;" : "+l"(acc) : "l"(a), "l"(b))

#define CP_ASYNC16(dst, src) \
    asm volatile("cp.async.cg.shared.global [%0], [%1], 16;" :: "r"(dst), "l"(src))
#define CP_COMMIT() asm volatile("cp.async.commit_group;")
#define CP_WAIT1()  asm volatile("cp.async.wait_group 1;")
#define CP_WAIT0()  asm volatile("cp.async.wait_group 0;")

__device__ __forceinline__ float f2lo(ull v) { return __uint_as_float((unsigned)(v & 0xffffffffULL)); }
__device__ __forceinline__ float f2hi(ull v) { return __uint_as_float((unsigned)(v >> 32)); }

// ---------------- warp MMA helpers (sm_80+ ISA, runs on sm_100) ----------------
__device__ __forceinline__ void ldsm_x4(uint32_t* r, unsigned addr) {
    asm volatile("ldmatrix.sync.aligned.m8n8.x4.shared.b16 {%0,%1,%2,%3}, [%4];"
        : "=r"(r[0]), "=r"(r[1]), "=r"(r[2]), "=r"(r[3]) : "r"(addr));
}
__device__ __forceinline__ void ldsm_x2(uint32_t* r, unsigned addr) {
    asm volatile("ldmatrix.sync.aligned.m8n8.x2.shared.b16 {%0,%1}, [%2];"
        : "=r"(r[0]), "=r"(r[1]) : "r"(addr));
}
__device__ __forceinline__ void mma_bf16(float* c, const uint32_t* a, const uint32_t* b) {
    asm volatile(
        "mma.sync.aligned.m16n8k16.row.col.f32.bf16.bf16.f32 "
        "{%0,%1,%2,%3}, {%4,%5,%6,%7}, {%8,%9}, {%0,%1,%2,%3};"
        : "+f"(c[0]), "+f"(c[1]), "+f"(c[2]), "+f"(c[3])
        : "r"(a[0]), "r"(a[1]), "r"(a[2]), "r"(a[3]), "r"(b[0]), "r"(b[1]));
}

// ---------------- device scratch ----------------
__device__ __align__(16) float  g_M2 [3*2048];
__device__ __align__(16) float  g_M34[3*16384];
__device__ __align__(16) __nv_bfloat16 g_UTh[(size_t)G3*H];   // U^T hi  [j][k]
__device__ __align__(16) __nv_bfloat16 g_UTl[(size_t)G3*H];   // U^T lo
__device__ __align__(16) __half g_P  [(size_t)BT*12288];
__device__ __align__(16) float  g_gi [(size_t)BT*G3];         // [t][b][3H]
__device__ __align__(16) __nv_bfloat16 g_hh[2][B*H];          // hidden hi (ping-pong)
__device__ __align__(16) __nv_bfloat16 g_hl[2][B*H];          // hidden lo
__device__ unsigned g_barc;
__device__ unsigned g_barg;

// ---------------- init ----------------
__global__ void init_kernel() {
    int idx = blockIdx.x * blockDim.x + threadIdx.x;
    unsigned* hh = (unsigned*)g_hh[0];
    unsigned* hl = (unsigned*)g_hl[0];
    for (int i = idx; i < B*H/2; i += gridDim.x * blockDim.x) { hh[i] = 0u; hl[i] = 0u; }
    if (idx == 0) { g_barc = 0u; g_barg = 0u; }
}

// ---------------- build M2, M34 from TT cores ----------------
__global__ void build_M_kernel(const float* __restrict__ c0,
                               const float* __restrict__ c1,
                               const float* __restrict__ c2,
                               const float* __restrict__ c3) {
    for (int idx = threadIdx.x; idx < 3*2048; idx += blockDim.x) {
        int r2 = idx & 3, o2 = (idx>>2)&3, o1 = (idx>>4)&3;
        int i2 = (idx>>6)&7, i1 = (idx>>9)&3, g = idx>>11;
        float s = 0.f;
        #pragma unroll
        for (int r1 = 0; r1 < 4; ++r1)
            s += c0[g*64 + i1*16 + o1*4 + r1] *
                 c1[g*512 + r1*128 + i2*16 + o2*4 + r2];
        g_M2[idx] = s;
    }
    for (int idx = threadIdx.x; idx < 3*16384; idx += blockDim.x) {
        int o4 = idx & 7, o3 = (idx>>3)&7, i4 = (idx>>6)&7;
        int i3 = (idx>>9)&7, r2 = (idx>>12)&3, g = idx>>14;
        float s = 0.f;
        #pragma unroll
        for (int r3 = 0; r3 < 4; ++r3)
            s += c2[g*1024 + r2*256 + i3*32 + o3*4 + r3] *
                 c3[g*256  + r3*64  + i4*8  + o4];
        g_M34[idx] = s;
    }
}

// ---------------- transpose U [H,G3] -> UT bf16 hi/lo [G3,H] ----------------
__global__ void build_UT_kernel(const float* __restrict__ U) {
    __shared__ float s[32][33];
    int j0 = blockIdx.x * 32;
    int k0 = blockIdx.y * 32;
    int tx = threadIdx.x, ty = threadIdx.y;
    #pragma unroll
    for (int r = ty; r < 32; r += 8)
        s[r][tx] = U[(size_t)(k0 + r) * G3 + j0 + tx];
    __syncthreads();
    #pragma unroll
    for (int r = ty; r < 32; r += 8) {
        float v = s[tx][r];
        __nv_bfloat16 hi = __float2bfloat16(v);
        size_t off = (size_t)(j0 + r) * H + k0 + tx;
        g_UTh[off] = hi;
        g_UTl[off] = __float2bfloat16(v - __bfloat162float(hi));
    }
}

// ---------------- TT stage A ----------------
#define TTA_SMEM (32*192*8 + 16*2048*4)   // 180224
__global__ void __launch_bounds__(256)
ttA_kernel(const float* __restrict__ X) {
    extern __shared__ __align__(16) float smA[];
    float2* sM = (float2*)smA;                 // [k(32)][r(192)] duplicated
    float*  sV = smA + 2*32*192;               // [bt(16)][2048]

    const int tid = threadIdx.x;
    const int bt0 = blockIdx.x * 16;

    for (int i = tid; i < 32*192; i += 256) {
        int k = i / 192, r = i - k*192;
        int g = r >> 6, ocr = r & 63;
        float v = g_M2[g*2048 + k*64 + ocr];
        sM[i] = make_float2(v, v);
    }
    {
        const float4* Xb = (const float4*)(X + (size_t)bt0 * D);
        float4* sv4 = (float4*)sV;
        #pragma unroll 8
        for (int q = 0; q < 32; ++q) sv4[tid + q*256] = Xb[tid + q*256];
    }
    __syncthreads();

    const int wid = tid >> 5, l = tid & 31;
    const int bts = wid*2 + (l >> 4);
    const int pq  = l & 15;
    const float* vb = sV + bts*2048 + pq*4;
    __half* Pb = g_P + (size_t)(bt0 + bts) * 12288;

    for (int rp = 0; rp < 12; ++rp) {
        const int r0 = rp * 16;
        ull acc[16][2];
        #pragma unroll
        for (int r = 0; r < 16; ++r) { acc[r][0] = 0ULL; acc[r][1] = 0ULL; }

        #pragma unroll 4
        for (int k = 0; k < 32; ++k) {
            ulonglong2 vv = *(const ulonglong2*)(vb + k*64);
            const ulonglong2* mrow = (const ulonglong2*)(sM + k*192 + r0);
            #pragma unroll
            for (int m = 0; m < 8; ++m) {
                ulonglong2 mm = mrow[m];
                FMA_F32X2(acc[2*m  ][0], vv.x, mm.x);
                FMA_F32X2(acc[2*m  ][1], vv.y, mm.x);
                FMA_F32X2(acc[2*m+1][0], vv.x, mm.y);
                FMA_F32X2(acc[2*m+1][1], vv.y, mm.y);
            }
        }
        #pragma unroll
        for (int rr = 0; rr < 16; ++rr) {
            int r = r0 + rr;
            int g = r >> 6, o = (r >> 2) & 15, r2 = r & 3;
            __half2 hA = __floats2half2_rn(f2lo(acc[rr][0]), f2hi(acc[rr][0]));
            __half2 hB = __floats2half2_rn(f2lo(acc[rr][1]), f2hi(acc[rr][1]));
            __half2* d2 = (__half2*)(Pb + ((size_t)(g*16 + o))*256 + r2*64 + pq*4);
            d2[0] = hA; d2[1] = hB;
        }
    }
}

// ---------------- TT stage B ----------------
#define TTB_SMEM (2*16*256*8 + 2*16*64*4)  // 73728
__device__ __forceinline__ void ttb_stageA(float2* Asd, int base, int tid,
                                           uint4 a0, uint4 a1) {
    const __half2* h0 = (const __half2*)&a0;
    const __half2* h1 = (const __half2*)&a1;
    #pragma unroll
    for (int q = 0; q < 4; ++q) {
        float2 f = __half22float2(h0[q]);
        Asd[(base + 2*q    )*256 + tid] = make_float2(f.x, f.x);
        Asd[(base + 2*q + 1)*256 + tid] = make_float2(f.y, f.y);
    }
    #pragma unroll
    for (int q = 0; q < 4; ++q) {
        float2 f = __half22float2(h1[q]);
        Asd[(base + 8 + 2*q    )*256 + tid] = make_float2(f.x, f.x);
        Asd[(base + 8 + 2*q + 1)*256 + tid] = make_float2(f.y, f.y);
    }
}

__global__ void __launch_bounds__(256)
ttB_kernel(const float* __restrict__ bi) {
    extern __shared__ __align__(16) float smB[];
    float2* Asd = (float2*)smB;
    float*  Bs  = smB + 2*2*16*256;

    const int tid = threadIdx.x;
    const int g   = blockIdx.y;
    const int m0  = blockIdx.x * 256;
    const int tx  = tid & 7;
    const int ty  = tid >> 3;

    const int am = m0 + tid;
    const __half* Ap = g_P + ((size_t)(am >> 4) * 48 + g*16 + (am & 15)) * 256;
    const int bk = tid >> 4, bcc = (tid & 15) * 4;
    const float* Bp = g_M34 + (size_t)g * 16384 + bk*64 + bcc;

    ull acc[8][4];
    #pragma unroll
    for (int i = 0; i < 8; ++i)
        #pragma unroll
        for (int n = 0; n < 4; ++n) acc[i][n] = 0ULL;

    uint4 a0 = *(const uint4*)(Ap);
    uint4 a1 = *(const uint4*)(Ap + 8);
    float4 b4 = *(const float4*)Bp;

    ttb_stageA(Asd, 0, tid, a0, a1);
    *(float4*)&Bs[bk*64 + bcc] = b4;
    __syncthreads();

    int buf = 0;
    for (int kt = 0; kt < 16; ++kt) {
        if (kt < 15) {
            a0 = *(const uint4*)(Ap + (kt+1)*16);
            a1 = *(const uint4*)(Ap + (kt+1)*16 + 8);
            b4 = *(const float4*)(Bp + (size_t)(kt+1)*16*64);
        }
        #pragma unroll
        for (int k = 0; k < 16; ++k) {
            const ulonglong2* ap = (const ulonglong2*)(Asd + (buf*16 + k)*256 + ty*8);
            ulonglong2 A01 = ap[0], A23 = ap[1], A45 = ap[2], A67 = ap[3];
            const ulonglong2* bp = (const ulonglong2*)(Bs + buf*1024 + k*64 + tx*8);
            ulonglong2 B01 = bp[0], B23 = bp[1];
            FMA_F32X2(acc[0][0], A01.x, B01.x); FMA_F32X2(acc[0][1], A01.x, B01.y);
            FMA_F32X2(acc[0][2], A01.x, B23.x); FMA_F32X2(acc[0][3], A01.x, B23.y);
            FMA_F32X2(acc[1][0], A01.y, B01.x); FMA_F32X2(acc[1][1], A01.y, B01.y);
            FMA_F32X2(acc[1][2], A01.y, B23.x); FMA_F32X2(acc[1][3], A01.y, B23.y);
            FMA_F32X2(acc[2][0], A23.x, B01.x); FMA_F32X2(acc[2][1], A23.x, B01.y);
            FMA_F32X2(acc[2][2], A23.x, B23.x); FMA_F32X2(acc[2][3], A23.x, B23.y);
            FMA_F32X2(acc[3][0], A23.y, B01.x); FMA_F32X2(acc[3][1], A23.y, B01.y);
            FMA_F32X2(acc[3][2], A23.y, B23.x); FMA_F32X2(acc[3][3], A23.y, B23.y);
            FMA_F32X2(acc[4][0], A45.x, B01.x); FMA_F32X2(acc[4][1], A45.x, B01.y);
            FMA_F32X2(acc[4][2], A45.x, B23.x); FMA_F32X2(acc[4][3], A45.x, B23.y);
            FMA_F32X2(acc[5][0], A45.y, B01.x); FMA_F32X2(acc[5][1], A45.y, B01.y);
            FMA_F32X2(acc[5][2], A45.y, B23.x); FMA_F32X2(acc[5][3], A45.y, B23.y);
            FMA_F32X2(acc[6][0], A67.x, B01.x); FMA_F32X2(acc[6][1], A67.x, B01.y);
            FMA_F32X2(acc[6][2], A67.x, B23.x); FMA_F32X2(acc[6][3], A67.x, B23.y);
            FMA_F32X2(acc[7][0], A67.y, B01.x); FMA_F32X2(acc[7][1], A67.y, B01.y);
            FMA_F32X2(acc[7][2], A67.y, B23.x); FMA_F32X2(acc[7][3], A67.y, B23.y);
        }
        if (kt < 15) {
            int nb = buf ^ 1;
            ttb_stageA(Asd, nb*16, tid, a0, a1);
            *(float4*)&Bs[nb*1024 + bk*64 + bcc] = b4;
        }
        __syncthreads();
        buf ^= 1;
    }

    #pragma unroll
    for (int i = 0; i < 8; ++i) {
        int m  = m0 + ty*8 + i;
        int bt = m >> 4, oo = m & 15;
        int bb = bt >> 8, tt = bt & 255;
        const float* bp2 = bi + g*1024 + oo*64 + tx*8;
        float4 o1 = make_float4(f2lo(acc[i][0]) + bp2[0], f2hi(acc[i][0]) + bp2[1],
                                f2lo(acc[i][1]) + bp2[2], f2hi(acc[i][1]) + bp2[3]);
        float4 o2 = make_float4(f2lo(acc[i][2]) + bp2[4], f2hi(acc[i][2]) + bp2[5],
                                f2lo(acc[i][3]) + bp2[6], f2hi(acc[i][3]) + bp2[7]);
        float* dst = g_gi + ((size_t)tt * B + bb) * G3 + g*1024 + oo*64 + tx*8;
        ((float4*)dst)[0] = o1;
        ((float4*)dst)[1] = o2;
    }
}

// ---------------- persistent mma.sync scan ----------------
// 128 blocks x 384 thr (12 warps = 4 M-tiles x 3 gates).
// Per step: D[64,24] = h[64,1024] x Uslice[24,1024]^T  (bf16 hi/lo, 3 products)
#define SCAN_BLOCKS 128
#define SCAN_THREADS 384
#define SC_BH 0                      // 24 x 2048B   (n rows, k, swizzled)
#define SC_BL 49152
#define SC_A  98304                  // 2 bufs x (hi 32768 + lo 32768)
#define SCAN_SMEM (98304 + 131072)   // 229376

__device__ __forceinline__ void stageA_chunk(const __nv_bfloat16* hh, const __nv_bfloat16* hl,
                                             unsigned sb, int ck, int buf, int tid) {
    const unsigned baseH = sb + (unsigned)SC_A + (unsigned)buf*65536u;
    const unsigned baseL = baseH + 32768u;
    for (int i = tid; i < 2048; i += SCAN_THREADS) {
        int b = i >> 5, u = i & 31;
        int us = (u & ~7) | ((u & 7) ^ (b & 7));
        unsigned off = (unsigned)(b*512 + us*16);
        const __nv_bfloat16* s1 = hh + (size_t)b*H + ck*256 + u*8;
        const __nv_bfloat16* s2 = hl + (size_t)b*H + ck*256 + u*8;
        CP_ASYNC16(baseH + off, s1);
        CP_ASYNC16(baseL + off, s2);
    }
}

__global__ void __launch_bounds__(SCAN_THREADS, 1)
scan_kernel(const float* __restrict__ bh) {
    extern __shared__ __align__(1024) char smem[];
    const unsigned sb = (unsigned)__cvta_generic_to_shared(smem);
    const int tid  = threadIdx.x;
    const int wid  = tid >> 5;
    const int lane = tid & 31;
    const int o0   = blockIdx.x * 8;
    const int wm   = wid & 3;            // M-tile (batches wm*16..+15)
    const int wg   = wid >> 2;           // gate / N-tile (0..2)

    // stage B = UT slice hi/lo (rows n = g*8+ol), swizzled for ldmatrix
    for (int i = tid; i < 3072; i += SCAN_THREADS) {
        int n = i >> 7, u = i & 127;
        int us = (u & ~7) | ((u & 7) ^ (n & 7));
        int g = n >> 3, ol = n & 7;
        size_t src = ((size_t)(g*H + o0 + ol))*H + (size_t)u*8;
        *(uint4*)(smem + SC_BH + n*2048 + us*16) = *(const uint4*)(g_UTh + src);
        *(uint4*)(smem + SC_BL + n*2048 + us*16) = *(const uint4*)(g_UTl + src);
    }
    __syncthreads();

    // per-lane ldmatrix parameters
    const int arow   = wm*16 + (lane & 15);
    const int kadd8  = lane >> 4;             // 0/1 -> k or k+8
    const unsigned arow_off = (unsigned)(arow * 512);
    const int arow7  = arow & 7;
    const int brow   = wg*8 + (lane & 7);
    const unsigned brow_off = (unsigned)(brow * 2048);
    const int brow7  = brow & 7;
    const int bk8    = (lane >> 3) & 1;

    // pointwise output mapping: out0 = tid, out1 = tid+384 (tid<128)
    const int b0o = tid >> 3,        ol0 = tid & 7;
    const int b1o = (tid + 384) >> 3, ol1 = tid & 7;   // (tid+384)&7 == tid&7
    float bh0v[3], bh1v[3];
    #pragma unroll
    for (int g = 0; g < 3; ++g) {
        bh0v[g] = bh[g*H + o0 + ol0];
        bh1v[g] = bh[g*H + o0 + ol1];
    }

    float* red = (float*)(smem + SC_A);       // [3][64][8] fp32, aliases A buf0

    for (int t = 0; t < T; ++t) {
        const __nv_bfloat16* hh = g_hh[t & 1];
        const __nv_bfloat16* hl = g_hl[t & 1];
        __nv_bfloat16* nhh = g_hh[(t & 1) ^ 1];
        __nv_bfloat16* nhl = g_hl[(t & 1) ^ 1];

        stageA_chunk(hh, hl, sb, 0, 0, tid);
        CP_COMMIT();

        // prefetch gi + h_old for this thread's outputs
        float gi0[3], gi1[3], hold0, hold1;
        {
            const float* gp0 = g_gi + ((size_t)t*B + b0o)*G3 + o0 + ol0;
            #pragma unroll
            for (int g = 0; g < 3; ++g) gi0[g] = __ldg(gp0 + g*H);
            hold0 = __bfloat162float(hh[(size_t)b0o*H + o0 + ol0])
                  + __bfloat162float(hl[(size_t)b0o*H + o0 + ol0]);
            if (tid < 128) {
                const float* gp1 = g_gi + ((size_t)t*B + b1o)*G3 + o0 + ol1;
                #pragma unroll
                for (int g = 0; g < 3; ++g) gi1[g] = __ldg(gp1 + g*H);
                hold1 = __bfloat162float(hh[(size_t)b1o*H + o0 + ol1])
                      + __bfloat162float(hl[(size_t)b1o*H + o0 + ol1]);
            }
        }

        float c[4] = {0.f, 0.f, 0.f, 0.f};

        #pragma unroll
        for (int ck = 0; ck < 4; ++ck) {
            if (ck < 3) {
                stageA_chunk(hh, hl, sb, ck+1, (ck+1)&1, tid);
                CP_COMMIT();
                CP_WAIT1();
            } else {
                CP_WAIT0();
            }
            __syncthreads();

            const unsigned aH = sb + (unsigned)SC_A + (unsigned)((ck&1)*65536);
            #pragma unroll
            for (int ks = 0; ks < 16; ++ks) {
                uint32_t ah[4], al[4], bhr[2], blr[2];
                int u  = ks*2 + kadd8;
                int us = (u & ~7) | ((u & 7) ^ arow7);
                unsigned aaddr = aH + arow_off + (unsigned)(us*16);
                ldsm_x4(ah, aaddr);
                ldsm_x4(al, aaddr + 32768u);
                int kg  = ck*32 + ks*2 + bk8;
                int bus = (kg & ~7) | ((kg & 7) ^ brow7);
                unsigned baddr = sb + (unsigned)SC_BH + brow_off + (unsigned)(bus*16);
                ldsm_x2(bhr, baddr);
                ldsm_x2(blr, baddr + 49152u);
                mma_bf16(c, ah, bhr);
                mma_bf16(c, al, bhr);
                mma_bf16(c, ah, blr);
            }
            __syncthreads();
        }

        // scatter C frags to red[g][b][ol]
        {
            int row = wm*16 + (lane >> 2);
            int col = (lane & 3) * 2;
            float* rg = red + wg*512;
            rg[row*8 + col]       = c[0];
            rg[row*8 + col + 1]   = c[1];
            rg[(row+8)*8 + col]     = c[2];
            rg[(row+8)*8 + col + 1] = c[3];
        }
        __syncthreads();

        // pointwise GRU update
        {
            float s0 = red[        b0o*8 + ol0];
            float s1 = red[ 512 +  b0o*8 + ol0];
            float s2 = red[1024 +  b0o*8 + ol0];
            float r  = 1.f / (1.f + __expf(-(gi0[0] + s0 + bh0v[0])));
            float z  = 1.f / (1.f + __expf(-(gi0[1] + s1 + bh0v[1])));
            float na = gi0[2] + r * (s2 + bh0v[2]);
            float te = __expf(2.f * na);
            float n  = 1.f - 2.f / (te + 1.f);
            float hn = (1.f - z) * n + z * hold0;
            __nv_bfloat16 hb = __float2bfloat16(hn);
            nhh[(size_t)b0o*H + o0 + ol0] = hb;
            nhl[(size_t)b0o*H + o0 + ol0] = __float2bfloat16(hn - __bfloat162float(hb));
            if (tid < 128) {
                float q0 = red[        b1o*8 + ol1];
                float q1 = red[ 512 +  b1o*8 + ol1];
                float q2 = red[1024 +  b1o*8 + ol1];
                float r1 = 1.f / (1.f + __expf(-(gi1[0] + q0 + bh1v[0])));
                float z1 = 1.f / (1.f + __expf(-(gi1[1] + q1 + bh1v[1])));
                float nb = gi1[2] + r1 * (q2 + bh1v[2]);
                float t2 = __expf(2.f * nb);
                float n1 = 1.f - 2.f / (t2 + 1.f);
                float h1 = (1.f - z1) * n1 + z1 * hold1;
                __nv_bfloat16 hb1 = __float2bfloat16(h1);
                nhh[(size_t)b1o*H + o0 + ol1] = hb1;
                nhl[(size_t)b1o*H + o0 + ol1] = __float2bfloat16(h1 - __bfloat162float(hb1));
            }
        }

        // grid barrier (release/acquire at L2, monotone counters)
        __syncthreads();
        if (tid == 0) {
            unsigned old;
            asm volatile("atom.add.release.gpu.u32 %0, [%1], 1;"
                         : "=r"(old) : "l"(&g_barc) : "memory");
            unsigned tgt = (unsigned)(t + 1);
            if (old == tgt * SCAN_BLOCKS - 1u) {
                asm volatile("st.release.gpu.u32 [%0], %1;" :: "l"(&g_barg), "r"(tgt) : "memory");
            } else {
                unsigned cur;
                do {
                    asm volatile("ld.acquire.gpu.u32 %0, [%1];" : "=r"(cur) : "l"(&g_barg) : "memory");
                } while (cur < tgt);
            }
        }
        __syncthreads();
    }
}

// ---------------- final FC + ReLU ----------------
__global__ void fc_kernel(const float* __restrict__ Wfc,
                          const float* __restrict__ bfc,
                          float* __restrict__ out) {
    int idx = blockIdx.x * blockDim.x + threadIdx.x;
    if (idx >= B * NC) return;
    int b = idx / NC, c = idx - b * NC;
    const __nv_bfloat16* hh = g_hh[0] + (size_t)b * H;   // T even -> final in buffer 0
    const __nv_bfloat16* hl = g_hl[0] + (size_t)b * H;
    float s = bfc[c];
    for (int k = 0; k < H; k += 8) {
        uint4 va = *(const uint4*)(hh + k);
        uint4 vb = *(const uint4*)(hl + k);
        const __nv_bfloat16* pa = (const __nv_bfloat16*)&va;
        const __nv_bfloat16* pb = (const __nv_bfloat16*)&vb;
        #pragma unroll
        for (int e = 0; e < 8; ++e) {
            float hv = __bfloat162float(pa[e]) + __bfloat162float(pb[e]);
            s += hv * Wfc[(size_t)(k + e) * NC + c];
        }
    }
    out[idx] = fmaxf(s, 0.f);
}

// ---------------- launcher ----------------
extern "C" void kernel_launch(void* const* d_in, const int* in_sizes, int n_in,
                              void* d_out, int out_size) {
    (void)in_sizes; (void)n_in; (void)out_size;
    const float* x    = (const float*)d_in[0];
    const float* c0   = (const float*)d_in[1];
    const float* c1   = (const float*)d_in[2];
    const float* c2   = (const float*)d_in[3];
    const float* c3   = (const float*)d_in[4];
    const float* bi   = (const float*)d_in[5];
    const float* U    = (const float*)d_in[6];
    const float* bh   = (const float*)d_in[7];
    const float* Wfc  = (const float*)d_in[8];
    const float* bfc  = (const float*)d_in[9];

    cudaFuncSetAttribute(ttA_kernel,  cudaFuncAttributeMaxDynamicSharedMemorySize, TTA_SMEM);
    cudaFuncSetAttribute(ttB_kernel,  cudaFuncAttributeMaxDynamicSharedMemorySize, TTB_SMEM);
    cudaFuncSetAttribute(scan_kernel, cudaFuncAttributeMaxDynamicSharedMemorySize, SCAN_SMEM);

    init_kernel<<<64, 256>>>();
    build_M_kernel<<<1, 256>>>(c0, c1, c2, c3);
    build_UT_kernel<<<dim3(96, 32), dim3(32, 8)>>>(U);
    ttA_kernel<<<BT/16, 256, TTA_SMEM>>>(x);
    ttB_kernel<<<dim3(BT*16/256, 3), 256, TTB_SMEM>>>(bi);
    scan_kernel<<<SCAN_BLOCKS, SCAN_THREADS, SCAN_SMEM>>>(bh);
    fc_kernel<<<(B * NC + 255) / 256, 256>>>(Wfc, bfc, (float*)d_out);
}

// round 10
// speedup vs baseline: 2.3294x; 1.0897x over previous
#include <cuda_runtime.h>
#include <cuda_fp16.h>
#include <cuda_bf16.h>
#include <math.h>
#include <stdint.h>

typedef unsigned long long ull;

// ---------------- problem constants ----------------
#define B   64
#define T   256
#define D   2048
#define H   1024
#define G3  3072
#define NC  1000
#define BT  (B*T)

#define FMA_F32X2(acc, a, b) \
    asm("fma.rn.f32x2 %0, %1, %2, %0;" : "+l"(acc) : "l"(a), "l"(b))

#define CP_ASYNC16(dst, src) \
    asm volatile("cp.async.cg.shared.global [%0], [%1], 16;" :: "r"(dst), "l"(src))
#define CP_COMMIT() asm volatile("cp.async.commit_group;")
#define CP_WAIT1()  asm volatile("cp.async.wait_group 1;")
#define CP_WAIT0()  asm volatile("cp.async.wait_group 0;")

__device__ __forceinline__ float f2lo(ull v) { return __uint_as_float((unsigned)(v & 0xffffffffULL)); }
__device__ __forceinline__ float f2hi(ull v) { return __uint_as_float((unsigned)(v >> 32)); }

// ---------------- warp MMA helpers (sm_80+ ISA, runs on sm_100) ----------------
__device__ __forceinline__ void ldsm_x4(uint32_t* r, unsigned addr) {
    asm volatile("ldmatrix.sync.aligned.m8n8.x4.shared.b16 {%0,%1,%2,%3}, [%4];"
        : "=r"(r[0]), "=r"(r[1]), "=r"(r[2]), "=r"(r[3]) : "r"(addr));
}
__device__ __forceinline__ void ldsm_x2(uint32_t* r, unsigned addr) {
    asm volatile("ldmatrix.sync.aligned.m8n8.x2.shared.b16 {%0,%1}, [%2];"
        : "=r"(r[0]), "=r"(r[1]) : "r"(addr));
}
__device__ __forceinline__ void mma_bf16(float* c, const uint32_t* a, const uint32_t* b) {
    asm volatile(
        "mma.sync.aligned.m16n8k16.row.col.f32.bf16.bf16.f32 "
        "{%0,%1,%2,%3}, {%4,%5,%6,%7}, {%8,%9}, {%0,%1,%2,%3};"
        : "+f"(c[0]), "+f"(c[1]), "+f"(c[2]), "+f"(c[3])
        : "r"(a[0]), "r"(a[1]), "r"(a[2]), "r"(a[3]), "r"(b[0]), "r"(b[1]));
}
__device__ __forceinline__ void mma_fp16(float* c, const uint32_t* a, const uint32_t* b) {
    asm volatile(
        "mma.sync.aligned.m16n8k16.row.col.f32.f16.f16.f32 "
        "{%0,%1,%2,%3}, {%4,%5,%6,%7}, {%8,%9}, {%0,%1,%2,%3};"
        : "+f"(c[0]), "+f"(c[1]), "+f"(c[2]), "+f"(c[3])
        : "r"(a[0]), "r"(a[1]), "r"(a[2]), "r"(a[3]), "r"(b[0]), "r"(b[1]));
}

// ---------------- device scratch ----------------
__device__ __align__(16) float  g_M2 [3*2048];
__device__ __align__(16) float  g_M34[3*16384];               // [g][k(256)][n(64)] fp32
__device__ __align__(16) __half g_M34h[3*16384];              // [g][n(64)][k(256)] fp16 hi
__device__ __align__(16) __half g_M34l[3*16384];              // [g][n(64)][k(256)] fp16 lo
__device__ __align__(16) __nv_bfloat16 g_UTh[(size_t)G3*H];   // U^T hi  [j][k]
__device__ __align__(16) __nv_bfloat16 g_UTl[(size_t)G3*H];   // U^T lo
__device__ __align__(16) __half g_P  [(size_t)BT*12288];
__device__ __align__(16) float  g_gi [(size_t)BT*G3];         // [t][b][3H]
__device__ __align__(16) __nv_bfloat16 g_hh[2][B*H];          // hidden hi (ping-pong)
__device__ __align__(16) __nv_bfloat16 g_hl[2][B*H];          // hidden lo
// tree barrier: 16 leaf counters (128B apart), one root, one generation word
__device__ unsigned g_leaf[16*32];
__device__ unsigned g_root;
__device__ unsigned g_gen;

// ---------------- init ----------------
__global__ void init_kernel() {
    int idx = blockIdx.x * blockDim.x + threadIdx.x;
    unsigned* hh = (unsigned*)g_hh[0];
    unsigned* hl = (unsigned*)g_hl[0];
    for (int i = idx; i < B*H/2; i += gridDim.x * blockDim.x) { hh[i] = 0u; hl[i] = 0u; }
    if (idx < 16*32) g_leaf[idx] = 0u;
    if (idx == 0) { g_root = 0u; g_gen = 0u; }
}

// ---------------- build M2, M34 from TT cores (+ fp16 hi/lo transpose) ----------------
__global__ void build_M_kernel(const float* __restrict__ c0,
                               const float* __restrict__ c1,
                               const float* __restrict__ c2,
                               const float* __restrict__ c3) {
    for (int idx = threadIdx.x; idx < 3*2048; idx += blockDim.x) {
        int r2 = idx & 3, o2 = (idx>>2)&3, o1 = (idx>>4)&3;
        int i2 = (idx>>6)&7, i1 = (idx>>9)&3, g = idx>>11;
        float s = 0.f;
        #pragma unroll
        for (int r1 = 0; r1 < 4; ++r1)
            s += c0[g*64 + i1*16 + o1*4 + r1] *
                 c1[g*512 + r1*128 + i2*16 + o2*4 + r2];
        g_M2[idx] = s;
    }
    for (int idx = threadIdx.x; idx < 3*16384; idx += blockDim.x) {
        int o4 = idx & 7, o3 = (idx>>3)&7, i4 = (idx>>6)&7;
        int i3 = (idx>>9)&7, r2 = (idx>>12)&3, g = idx>>14;
        float s = 0.f;
        #pragma unroll
        for (int r3 = 0; r3 < 4; ++r3)
            s += c2[g*1024 + r2*256 + i3*32 + o3*4 + r3] *
                 c3[g*256  + r3*64  + i4*8  + o4];
        g_M34[idx] = s;
    }
    __syncthreads();
    // transpose to [g][n][k] fp16 hi/lo for HMMA ttB
    for (int idx = threadIdx.x; idx < 3*16384; idx += blockDim.x) {
        int g = idx >> 14, rem = idx & 16383;
        int n = rem >> 8, k = rem & 255;
        float v = g_M34[g*16384 + k*64 + n];
        __half hi = __float2half_rn(v);
        g_M34h[idx] = hi;
        g_M34l[idx] = __float2half_rn(v - __half2float(hi));
    }
}

// ---------------- transpose U [H,G3] -> UT bf16 hi/lo [G3,H] ----------------
__global__ void build_UT_kernel(const float* __restrict__ U) {
    __shared__ float s[32][33];
    int j0 = blockIdx.x * 32;
    int k0 = blockIdx.y * 32;
    int tx = threadIdx.x, ty = threadIdx.y;
    #pragma unroll
    for (int r = ty; r < 32; r += 8)
        s[r][tx] = U[(size_t)(k0 + r) * G3 + j0 + tx];
    __syncthreads();
    #pragma unroll
    for (int r = ty; r < 32; r += 8) {
        float v = s[tx][r];
        __nv_bfloat16 hi = __float2bfloat16(v);
        size_t off = (size_t)(j0 + r) * H + k0 + tx;
        g_UTh[off] = hi;
        g_UTl[off] = __float2bfloat16(v - __bfloat162float(hi));
    }
}

// ---------------- TT stage A (FMA2, at its issue ceiling) ----------------
#define TTA_SMEM (32*192*8 + 16*2048*4)   // 180224
__global__ void __launch_bounds__(256)
ttA_kernel(const float* __restrict__ X) {
    extern __shared__ __align__(16) float smA[];
    float2* sM = (float2*)smA;                 // [k(32)][r(192)] duplicated
    float*  sV = smA + 2*32*192;               // [bt(16)][2048]

    const int tid = threadIdx.x;
    const int bt0 = blockIdx.x * 16;

    for (int i = tid; i < 32*192; i += 256) {
        int k = i / 192, r = i - k*192;
        int g = r >> 6, ocr = r & 63;
        float v = g_M2[g*2048 + k*64 + ocr];
        sM[i] = make_float2(v, v);
    }
    {
        const float4* Xb = (const float4*)(X + (size_t)bt0 * D);
        float4* sv4 = (float4*)sV;
        #pragma unroll 8
        for (int q = 0; q < 32; ++q) sv4[tid + q*256] = Xb[tid + q*256];
    }
    __syncthreads();

    const int wid = tid >> 5, l = tid & 31;
    const int bts = wid*2 + (l >> 4);
    const int pq  = l & 15;
    const float* vb = sV + bts*2048 + pq*4;
    __half* Pb = g_P + (size_t)(bt0 + bts) * 12288;

    for (int rp = 0; rp < 12; ++rp) {
        const int r0 = rp * 16;
        ull acc[16][2];
        #pragma unroll
        for (int r = 0; r < 16; ++r) { acc[r][0] = 0ULL; acc[r][1] = 0ULL; }

        #pragma unroll 4
        for (int k = 0; k < 32; ++k) {
            ulonglong2 vv = *(const ulonglong2*)(vb + k*64);
            const ulonglong2* mrow = (const ulonglong2*)(sM + k*192 + r0);
            #pragma unroll
            for (int m = 0; m < 8; ++m) {
                ulonglong2 mm = mrow[m];
                FMA_F32X2(acc[2*m  ][0], vv.x, mm.x);
                FMA_F32X2(acc[2*m  ][1], vv.y, mm.x);
                FMA_F32X2(acc[2*m+1][0], vv.x, mm.y);
                FMA_F32X2(acc[2*m+1][1], vv.y, mm.y);
            }
        }
        #pragma unroll
        for (int rr = 0; rr < 16; ++rr) {
            int r = r0 + rr;
            int g = r >> 6, o = (r >> 2) & 15, r2 = r & 3;
            __half2 hA = __floats2half2_rn(f2lo(acc[rr][0]), f2hi(acc[rr][0]));
            __half2 hB = __floats2half2_rn(f2lo(acc[rr][1]), f2hi(acc[rr][1]));
            __half2* d2 = (__half2*)(Pb + ((size_t)(g*16 + o))*256 + r2*64 + pq*4);
            d2[0] = hA; d2[1] = hB;
        }
    }
}

// ---------------- TT stage B: HMMA ----------------
// per gate g: C[M=BT*16, 64] = P_g[M,256] @ M34g^T, fp16 A, fp16 hi/lo B.
// block: 128 M rows, 8 warps = 4M(32) x 2N(32). K=256 fully staged.
#define TTB_SMEM (65536 + 32768 + 32768)   // A 64KB | Bh 32KB | Bl 32KB
__global__ void __launch_bounds__(256)
ttB_kernel(const float* __restrict__ bi) {
    extern __shared__ __align__(1024) char smB[];
    const unsigned sb = (unsigned)__cvta_generic_to_shared(smB);
    const int tid = threadIdx.x;
    const int g   = blockIdx.y;
    const int m0  = blockIdx.x * 128;

    // stage A (P rows), swizzled for ldmatrix
    for (int i = tid; i < 4096; i += 256) {
        int r = i >> 5, u = i & 31;
        int us = (u & ~7) | ((u & 7) ^ (r & 7));
        int m = m0 + r;
        const __half* src = g_P + ((size_t)(m >> 4)*48 + g*16 + (m & 15))*256 + u*8;
        CP_ASYNC16(sb + (unsigned)(r*512 + us*16), src);
    }
    // stage B hi/lo ([n][k] rows)
    for (int i = tid; i < 2048; i += 256) {
        int n = i >> 5, u = i & 31;
        int us = (u & ~7) | ((u & 7) ^ (n & 7));
        const __half* s1 = g_M34h + ((size_t)g*64 + n)*256 + u*8;
        const __half* s2 = g_M34l + ((size_t)g*64 + n)*256 + u*8;
        CP_ASYNC16(sb + 65536u + (unsigned)(n*512 + us*16), s1);
        CP_ASYNC16(sb + 98304u + (unsigned)(n*512 + us*16), s2);
    }
    CP_COMMIT(); CP_WAIT0();
    __syncthreads();

    const int wid = tid >> 5, lane = tid & 31;
    const int wm = wid & 3, wn = wid >> 2;
    const int lrow = lane & 15, lk = lane >> 4;

    float c[2][4][4];
    #pragma unroll
    for (int ms = 0; ms < 2; ++ms)
        #pragma unroll
        for (int j = 0; j < 4; ++j)
            #pragma unroll
            for (int e = 0; e < 4; ++e) c[ms][j][e] = 0.f;

    #pragma unroll
    for (int ks = 0; ks < 16; ++ks) {
        const int u = ks*2 + lk;
        uint32_t a[2][4], bh4[2][4], bl4[2][4];
        #pragma unroll
        for (int ms = 0; ms < 2; ++ms) {
            int r = wm*32 + ms*16 + lrow;
            int us = (u & ~7) | ((u & 7) ^ (r & 7));
            ldsm_x4(a[ms], sb + (unsigned)(r*512 + us*16));
        }
        #pragma unroll
        for (int ns = 0; ns < 2; ++ns) {
            int n = wn*32 + ns*16 + lrow;
            int us = (u & ~7) | ((u & 7) ^ (n & 7));
            ldsm_x4(bh4[ns], sb + 65536u + (unsigned)(n*512 + us*16));
            ldsm_x4(bl4[ns], sb + 98304u + (unsigned)(n*512 + us*16));
        }
        #pragma unroll
        for (int ms = 0; ms < 2; ++ms)
            #pragma unroll
            for (int j = 0; j < 4; ++j) {
                uint32_t bfh[2] = { bh4[j>>1][j&1], bh4[j>>1][(j&1)+2] };
                uint32_t bfl[2] = { bl4[j>>1][j&1], bl4[j>>1][(j&1)+2] };
                mma_fp16(c[ms][j], a[ms], bfh);
                mma_fp16(c[ms][j], a[ms], bfl);
            }
    }

    // epilogue: bias + scatter to gi[t][b][3H]
    #pragma unroll
    for (int ms = 0; ms < 2; ++ms) {
        #pragma unroll
        for (int j = 0; j < 4; ++j) {
            int nn = wn*32 + j*8 + (lane & 3)*2;
            #pragma unroll
            for (int half = 0; half < 2; ++half) {
                int r = wm*32 + ms*16 + (lane >> 2) + half*8;
                int m = m0 + r;
                int bt = m >> 4, oo = m & 15;
                int bb = bt >> 8, tt = bt & 255;
                const float* bp = bi + g*1024 + oo*64 + nn;
                float2 v;
                v.x = c[ms][j][half*2]     + bp[0];
                v.y = c[ms][j][half*2 + 1] + bp[1];
                *(float2*)(g_gi + ((size_t)tt*B + bb)*G3 + g*1024 + oo*64 + nn) = v;
            }
        }
    }
}

// ---------------- persistent mma.sync scan ----------------
// 128 blocks x 384 thr (12 warps = 4 M-tiles x 3 gates).
#define SCAN_BLOCKS 128
#define SCAN_THREADS 384
#define SC_BH 0                      // 24 x 2048B   (n rows, k, swizzled)
#define SC_BL 49152
#define SC_A  98304                  // 2 bufs x (hi 32768 + lo 32768)
#define SCAN_SMEM (98304 + 131072)   // 229376

__device__ __forceinline__ void stageA_chunk(const __nv_bfloat16* hh, const __nv_bfloat16* hl,
                                             unsigned sb, int ck, int buf, int tid) {
    const unsigned baseH = sb + (unsigned)SC_A + (unsigned)buf*65536u;
    const unsigned baseL = baseH + 32768u;
    for (int i = tid; i < 2048; i += SCAN_THREADS) {
        int b = i >> 5, u = i & 31;
        int us = (u & ~7) | ((u & 7) ^ (b & 7));
        unsigned off = (unsigned)(b*512 + us*16);
        const __nv_bfloat16* s1 = hh + (size_t)b*H + ck*256 + u*8;
        const __nv_bfloat16* s2 = hl + (size_t)b*H + ck*256 + u*8;
        CP_ASYNC16(baseH + off, s1);
        CP_ASYNC16(baseL + off, s2);
    }
}

__global__ void __launch_bounds__(SCAN_THREADS, 1)
scan_kernel(const float* __restrict__ bh) {
    extern __shared__ __align__(1024) char smem[];
    const unsigned sb = (unsigned)__cvta_generic_to_shared(smem);
    const int tid  = threadIdx.x;
    const int wid  = tid >> 5;
    const int lane = tid & 31;
    const int o0   = blockIdx.x * 8;
    const int wm   = wid & 3;            // M-tile (batches wm*16..+15)
    const int wg   = wid >> 2;           // gate / N-tile (0..2)

    // stage B = UT slice hi/lo (rows n = g*8+ol), swizzled for ldmatrix
    for (int i = tid; i < 3072; i += SCAN_THREADS) {
        int n = i >> 7, u = i & 127;
        int us = (u & ~7) | ((u & 7) ^ (n & 7));
        int g = n >> 3, ol = n & 7;
        size_t src = ((size_t)(g*H + o0 + ol))*H + (size_t)u*8;
        *(uint4*)(smem + SC_BH + n*2048 + us*16) = *(const uint4*)(g_UTh + src);
        *(uint4*)(smem + SC_BL + n*2048 + us*16) = *(const uint4*)(g_UTl + src);
    }
    __syncthreads();

    // per-lane ldmatrix parameters
    const int arow   = wm*16 + (lane & 15);
    const int kadd8  = lane >> 4;
    const unsigned arow_off = (unsigned)(arow * 512);
    const int arow7  = arow & 7;
    const int brow   = wg*8 + (lane & 7);
    const unsigned brow_off = (unsigned)(brow * 2048);
    const int brow7  = brow & 7;
    const int bk8    = (lane >> 3) & 1;

    // pointwise output mapping: out0 = tid, out1 = tid+384 (tid<128)
    const int b0o = tid >> 3,        ol0 = tid & 7;
    const int b1o = (tid + 384) >> 3, ol1 = tid & 7;
    float bh0v[3], bh1v[3];
    #pragma unroll
    for (int g = 0; g < 3; ++g) {
        bh0v[g] = bh[g*H + o0 + ol0];
        bh1v[g] = bh[g*H + o0 + ol1];
    }

    float* red = (float*)(smem + SC_A);       // [3][64][8] fp32, aliases A buf0
    const int leaf = blockIdx.x >> 3;         // 16 leaves of 8 blocks

    for (int t = 0; t < T; ++t) {
        const __nv_bfloat16* hh = g_hh[t & 1];
        const __nv_bfloat16* hl = g_hl[t & 1];
        __nv_bfloat16* nhh = g_hh[(t & 1) ^ 1];
        __nv_bfloat16* nhl = g_hl[(t & 1) ^ 1];

        stageA_chunk(hh, hl, sb, 0, 0, tid);
        CP_COMMIT();

        float gi0[3], gi1[3], hold0, hold1;
        {
            const float* gp0 = g_gi + ((size_t)t*B + b0o)*G3 + o0 + ol0;
            #pragma unroll
            for (int g = 0; g < 3; ++g) gi0[g] = __ldg(gp0 + g*H);
            hold0 = __bfloat162float(hh[(size_t)b0o*H + o0 + ol0])
                  + __bfloat162float(hl[(size_t)b0o*H + o0 + ol0]);
            if (tid < 128) {
                const float* gp1 = g_gi + ((size_t)t*B + b1o)*G3 + o0 + ol1;
                #pragma unroll
                for (int g = 0; g < 3; ++g) gi1[g] = __ldg(gp1 + g*H);
                hold1 = __bfloat162float(hh[(size_t)b1o*H + o0 + ol1])
                      + __bfloat162float(hl[(size_t)b1o*H + o0 + ol1]);
            }
        }

        float c[4] = {0.f, 0.f, 0.f, 0.f};

        #pragma unroll
        for (int ck = 0; ck < 4; ++ck) {
            if (ck < 3) {
                stageA_chunk(hh, hl, sb, ck+1, (ck+1)&1, tid);
                CP_COMMIT();
                CP_WAIT1();
            } else {
                CP_WAIT0();
            }
            __syncthreads();

            const unsigned aH = sb + (unsigned)SC_A + (unsigned)((ck&1)*65536);
            #pragma unroll
            for (int ks = 0; ks < 16; ++ks) {
                uint32_t ah[4], al[4], bhr[2], blr[2];
                int u  = ks*2 + kadd8;
                int us = (u & ~7) | ((u & 7) ^ arow7);
                unsigned aaddr = aH + arow_off + (unsigned)(us*16);
                ldsm_x4(ah, aaddr);
                ldsm_x4(al, aaddr + 32768u);
                int kg  = ck*32 + ks*2 + bk8;
                int bus = (kg & ~7) | ((kg & 7) ^ brow7);
                unsigned baddr = sb + (unsigned)SC_BH + brow_off + (unsigned)(bus*16);
                ldsm_x2(bhr, baddr);
                ldsm_x2(blr, baddr + 49152u);
                mma_bf16(c, ah, bhr);
                mma_bf16(c, al, bhr);
                mma_bf16(c, ah, blr);
            }
            __syncthreads();
        }

        // scatter C frags to red[g][b][ol]
        {
            int row = wm*16 + (lane >> 2);
            int col = (lane & 3) * 2;
            float* rg = red + wg*512;
            rg[row*8 + col]       = c[0];
            rg[row*8 + col + 1]   = c[1];
            rg[(row+8)*8 + col]     = c[2];
            rg[(row+8)*8 + col + 1] = c[3];
        }
        __syncthreads();

        // pointwise GRU update
        {
            float s0 = red[        b0o*8 + ol0];
            float s1 = red[ 512 +  b0o*8 + ol0];
            float s2 = red[1024 +  b0o*8 + ol0];
            float r  = 1.f / (1.f + __expf(-(gi0[0] + s0 + bh0v[0])));
            float z  = 1.f / (1.f + __expf(-(gi0[1] + s1 + bh0v[1])));
            float na = gi0[2] + r * (s2 + bh0v[2]);
            float te = __expf(2.f * na);
            float n  = 1.f - 2.f / (te + 1.f);
            float hn = (1.f - z) * n + z * hold0;
            __nv_bfloat16 hb = __float2bfloat16(hn);
            nhh[(size_t)b0o*H + o0 + ol0] = hb;
            nhl[(size_t)b0o*H + o0 + ol0] = __float2bfloat16(hn - __bfloat162float(hb));
            if (tid < 128) {
                float q0 = red[        b1o*8 + ol1];
                float q1 = red[ 512 +  b1o*8 + ol1];
                float q2 = red[1024 +  b1o*8 + ol1];
                float r1 = 1.f / (1.f + __expf(-(gi1[0] + q0 + bh1v[0])));
                float z1 = 1.f / (1.f + __expf(-(gi1[1] + q1 + bh1v[1])));
                float nb = gi1[2] + r1 * (q2 + bh1v[2]);
                float t2 = __expf(2.f * nb);
                float n1 = 1.f - 2.f / (t2 + 1.f);
                float h1 = (1.f - z1) * n1 + z1 * hold1;
                __nv_bfloat16 hb1 = __float2bfloat16(h1);
                nhh[(size_t)b1o*H + o0 + ol1] = hb1;
                nhl[(size_t)b1o*H + o0 + ol1] = __float2bfloat16(h1 - __bfloat162float(hb1));
            }
        }

        // two-level tree grid barrier (acq_rel, monotone counters)
        __syncthreads();
        if (tid == 0) {
            unsigned tgt = (unsigned)(t + 1);
            unsigned old;
            asm volatile("atom.add.acq_rel.gpu.u32 %0, [%1], 1;"
                         : "=r"(old) : "l"(&g_leaf[leaf*32]) : "memory");
            if (old == tgt*8u - 1u) {
                unsigned rold;
                asm volatile("atom.add.acq_rel.gpu.u32 %0, [%1], 1;"
                             : "=r"(rold) : "l"(&g_root) : "memory");
                if (rold == tgt*16u - 1u) {
                    asm volatile("st.release.gpu.u32 [%0], %1;" :: "l"(&g_gen), "r"(tgt) : "memory");
                }
            }
            unsigned cur;
            do {
                asm volatile("ld.acquire.gpu.u32 %0, [%1];" : "=r"(cur) : "l"(&g_gen) : "memory");
            } while (cur < tgt);
        }
        __syncthreads();
    }
}

// ---------------- final FC + ReLU ----------------
__global__ void fc_kernel(const float* __restrict__ Wfc,
                          const float* __restrict__ bfc,
                          float* __restrict__ out) {
    int idx = blockIdx.x * blockDim.x + threadIdx.x;
    if (idx >= B * NC) return;
    int b = idx / NC, c = idx - b * NC;
    const __nv_bfloat16* hh = g_hh[0] + (size_t)b * H;   // T even -> final in buffer 0
    const __nv_bfloat16* hl = g_hl[0] + (size_t)b * H;
    float s = bfc[c];
    for (int k = 0; k < H; k += 8) {
        uint4 va = *(const uint4*)(hh + k);
        uint4 vb = *(const uint4*)(hl + k);
        const __nv_bfloat16* pa = (const __nv_bfloat16*)&va;
        const __nv_bfloat16* pb = (const __nv_bfloat16*)&vb;
        #pragma unroll
        for (int e = 0; e < 8; ++e) {
            float hv = __bfloat162float(pa[e]) + __bfloat162float(pb[e]);
            s += hv * Wfc[(size_t)(k + e) * NC + c];
        }
    }
    out[idx] = fmaxf(s, 0.f);
}

// ---------------- launcher ----------------
extern "C" void kernel_launch(void* const* d_in, const int* in_sizes, int n_in,
                              void* d_out, int out_size) {
    (void)in_sizes; (void)n_in; (void)out_size;
    const float* x    = (const float*)d_in[0];
    const float* c0   = (const float*)d_in[1];
    const float* c1   = (const float*)d_in[2];
    const float* c2   = (const float*)d_in[3];
    const float* c3   = (const float*)d_in[4];
    const float* bi   = (const float*)d_in[5];
    const float* U    = (const float*)d_in[6];
    const float* bh   = (const float*)d_in[7];
    const float* Wfc  = (const float*)d_in[8];
    const float* bfc  = (const float*)d_in[9];

    cudaFuncSetAttribute(ttA_kernel,  cudaFuncAttributeMaxDynamicSharedMemorySize, TTA_SMEM);
    cudaFuncSetAttribute(ttB_kernel,  cudaFuncAttributeMaxDynamicSharedMemorySize, TTB_SMEM);
    cudaFuncSetAttribute(scan_kernel, cudaFuncAttributeMaxDynamicSharedMemorySize, SCAN_SMEM);

    init_kernel<<<64, 256>>>();
    build_M_kernel<<<1, 256>>>(c0, c1, c2, c3);
    build_UT_kernel<<<dim3(96, 32), dim3(32, 8)>>>(U);
    ttA_kernel<<<BT/16, 256, TTA_SMEM>>>(x);
    ttB_kernel<<<dim3(BT*16/128, 3), 256, TTB_SMEM>>>(bi);
    scan_kernel<<<SCAN_BLOCKS, SCAN_THREADS, SCAN_SMEM>>>(bh);
    fc_kernel<<<(B * NC + 255) / 256, 256>>>(Wfc, bfc, (float*)d_out);
}